// round 12
// baseline (speedup 1.0000x reference)
#include <cuda_runtime.h>
#include <cuda_bf16.h>
#include <cstdint>
#include <math.h>

#define B 512
#define IN_DIM 1024
#define H 512
#define E_DIM 512
#define V 2048
#define MAX_LEN 32
#define L 33
#define G4H (4 * H)

// ---------------- scratch (no allocations allowed) ----------------
__device__ float g_h[B * H];
__device__ float g_c[B * H];
__device__ float g_Pg[(size_t)B * G4H];
__device__ float g_logits[(size_t)2 * B * V];
__device__ float2 g_mls[2 * B];
__device__ float g_eproj[(size_t)V * G4H];
__device__ float g_sosproj[G4H];
// bf16x3 split operands for tensor-core step GEMM
__device__ __nv_bfloat16 g_A0[B * H];
__device__ __nv_bfloat16 g_A1[B * H];
__device__ __nv_bfloat16 g_A2[B * H];
__device__ __nv_bfloat16 g_Wt0[(size_t)4096 * 512];   // [n][k] = Wcat[k][n]
__device__ __nv_bfloat16 g_Wt1[(size_t)4096 * 512];
__device__ __nv_bfloat16 g_Wt2[(size_t)4096 * 512];

// ---------------- threefry2x32 ----------------
__host__ __device__ __forceinline__ uint32_t rotl32(uint32_t v, int d) {
    return (v << d) | (v >> (32 - d));
}
__host__ __device__ __forceinline__ void threefry2x32(uint32_t k0, uint32_t k1,
                                                      uint32_t x0, uint32_t x1,
                                                      uint32_t& o0, uint32_t& o1) {
    uint32_t ks2 = k0 ^ k1 ^ 0x1BD11BDAu;
    x0 += k0; x1 += k1;
#define TF_R(r) { x0 += x1; x1 = rotl32(x1, r); x1 ^= x0; }
    TF_R(13) TF_R(15) TF_R(26) TF_R(6)
    x0 += k1; x1 += ks2 + 1u;
    TF_R(17) TF_R(29) TF_R(16) TF_R(24)
    x0 += ks2; x1 += k0 + 2u;
    TF_R(13) TF_R(15) TF_R(26) TF_R(6)
    x0 += k0; x1 += k1 + 3u;
    TF_R(17) TF_R(29) TF_R(16) TF_R(24)
    x0 += k1; x1 += ks2 + 4u;
    TF_R(13) TF_R(15) TF_R(26) TF_R(6)
    x0 += ks2; x1 += k0 + 5u;
#undef TF_R
    o0 = x0; o1 = x1;
}

__device__ __forceinline__ float sigmoidf_(float x) {
    return 0.5f + 0.5f * tanhf(0.5f * x);
}

// ---------------- packed f32x2 helpers (fp32 gemms) ----------------
__device__ __forceinline__ void ffma2(unsigned long long& acc, unsigned long long a,
                                      unsigned long long b) {
    asm("fma.rn.f32x2 %0, %1, %2, %0;" : "+l"(acc) : "l"(a), "l"(b));
}
__device__ __forceinline__ unsigned long long dup2(float w) {
    unsigned long long r;
    asm("mov.b64 %0, {%1, %1};" : "=l"(r) : "r"(__float_as_uint(w)));
    return r;
}
__device__ __forceinline__ float2 unpack2(unsigned long long v) {
    float2 f;
    asm("mov.b64 {%0, %1}, %2;" : "=f"(f.x), "=f"(f.y) : "l"(v));
    return f;
}

__device__ __forceinline__ uint32_t smem_to_u32(const void* p) {
    uint32_t a;
    asm("{ .reg .u64 t; cvta.to.shared.u64 t, %1; cvt.u32.u64 %0, t; }" : "=r"(a) : "l"(p));
    return a;
}

// bf16x3 split
__device__ __forceinline__ void split3(float v, __nv_bfloat16& b0, __nv_bfloat16& b1,
                                       __nv_bfloat16& b2) {
    b0 = __float2bfloat16(v);
    float r1 = v - __bfloat162float(b0);
    b1 = __float2bfloat16(r1);
    float r2 = r1 - __bfloat162float(b1);
    b2 = __float2bfloat16(r2);
}

// ================= HMMA step GEMM =================
// C[512, 4096] = h @ [w_hh | out_w] via mma.sync.m16n8k16.bf16, 6 split products.
// CTA tile 128x128, 8 warps (4 m x 2 n), warp tile 32x64 = 2x8 mma tiles.
// Smem A/W tiles 128 rows x 32 bf16, row stride 40 bf16 (80 B, ldmatrix
// conflict-free: banks r*20 mod 32 distinct). 96 iterations (6 products x 16
// k-chunks of 32), register-prefetch double buffer.
#define MM_ASTRB 80           // bytes per smem row
#define MM_TILEB 10240        // 128 * 80
#define MM_SMEM  (4 * MM_TILEB)   // A[2] + W[2] = 40960

__global__ __launch_bounds__(256) void gemmMMA_kernel(
    float* __restrict__ Pg, float* __restrict__ logits_t, const float* __restrict__ out_b)
{
    extern __shared__ char smem[];
    uint32_t smb = smem_to_u32(smem);

    const int tid = threadIdx.x;
    const int lane = tid & 31;
    const int w = tid >> 5;
    const int wm = w & 3;            // 0..3  -> warp rows at wm*32
    const int wn = w >> 2;           // 0..1  -> warp cols at wn*64
    const int m0 = blockIdx.y * 128;
    const int n0 = blockIdx.x * 128;

    const int lrow = tid >> 1;       // 0..127 (loader row)
    const int lhalf = tid & 1;       // 0..1   (16-bf16 half)

    float c[2][8][4];
#pragma unroll
    for (int mt = 0; mt < 2; mt++)
#pragma unroll
        for (int nt = 0; nt < 8; nt++)
#pragma unroll
            for (int i = 0; i < 4; i++) c[mt][nt][i] = 0.f;

    // slab select per product s = it>>4
    auto a_ptr = [&](int it) -> const uint4* {
        int s = it >> 4; int kc = it & 15;
        const __nv_bfloat16* Ab = (s == 2 || s == 3) ? g_A1 : ((s == 5) ? g_A2 : g_A0);
        return reinterpret_cast<const uint4*>(Ab + (size_t)(m0 + lrow) * 512 + kc * 32 + lhalf * 16);
    };
    auto w_ptr = [&](int it) -> const uint4* {
        int s = it >> 4; int kc = it & 15;
        const __nv_bfloat16* Wb = (s == 1 || s == 3) ? g_Wt1 : ((s == 4) ? g_Wt2 : g_Wt0);
        return reinterpret_cast<const uint4*>(Wb + (size_t)(n0 + lrow) * 512 + kc * 32 + lhalf * 16);
    };

    uint4 pa0, pa1, pw0, pw1;
    {
        const uint4* ap = a_ptr(0); pa0 = ap[0]; pa1 = ap[1];
        const uint4* wp = w_ptr(0); pw0 = wp[0]; pw1 = wp[1];
    }

    const uint32_t sts_off = lrow * MM_ASTRB + lhalf * 32;
    const int q = lane >> 3, r = lane & 7;

    for (int it = 0; it < 96; ++it) {
        int buf = it & 1;
        uint32_t ab = smb + buf * MM_TILEB;
        uint32_t wb = smb + 2 * MM_TILEB + buf * MM_TILEB;
        // store prefetched tile
        asm volatile("st.shared.v4.b32 [%0], {%1,%2,%3,%4};" ::
            "r"(ab + sts_off), "r"(pa0.x), "r"(pa0.y), "r"(pa0.z), "r"(pa0.w) : "memory");
        asm volatile("st.shared.v4.b32 [%0], {%1,%2,%3,%4};" ::
            "r"(ab + sts_off + 16), "r"(pa1.x), "r"(pa1.y), "r"(pa1.z), "r"(pa1.w) : "memory");
        asm volatile("st.shared.v4.b32 [%0], {%1,%2,%3,%4};" ::
            "r"(wb + sts_off), "r"(pw0.x), "r"(pw0.y), "r"(pw0.z), "r"(pw0.w) : "memory");
        asm volatile("st.shared.v4.b32 [%0], {%1,%2,%3,%4};" ::
            "r"(wb + sts_off + 16), "r"(pw1.x), "r"(pw1.y), "r"(pw1.z), "r"(pw1.w) : "memory");
        __syncthreads();

        if (it + 1 < 96) {
            const uint4* ap = a_ptr(it + 1); pa0 = ap[0]; pa1 = ap[1];
            const uint4* wp = w_ptr(it + 1); pw0 = wp[0]; pw1 = wp[1];
        }

#pragma unroll
        for (int kkstep = 0; kkstep < 2; ++kkstep) {
            int kb = kkstep * 32;    // byte offset of k-half-chunk (16 bf16)
            // A fragments: 2 m-tiles
            uint32_t a[2][4];
#pragma unroll
            for (int mt = 0; mt < 2; mt++) {
                uint32_t addr = ab + (wm * 32 + mt * 16 + (q & 1) * 8 + r) * MM_ASTRB
                              + kb + (q >> 1) * 16;
                asm volatile("ldmatrix.sync.aligned.m8n8.x4.shared.b16 {%0,%1,%2,%3}, [%4];"
                    : "=r"(a[mt][0]), "=r"(a[mt][1]), "=r"(a[mt][2]), "=r"(a[mt][3])
                    : "r"(addr));
            }
            // B fragments: 8 n-tiles (2 per ldmatrix.x4)
            uint32_t bfr[8][2];
#pragma unroll
            for (int ng = 0; ng < 4; ng++) {
                uint32_t addr = wb + (wn * 64 + ng * 16 + (q >> 1) * 8 + r) * MM_ASTRB
                              + kb + (q & 1) * 16;
                uint32_t r0, r1, r2, r3;
                asm volatile("ldmatrix.sync.aligned.m8n8.x4.shared.b16 {%0,%1,%2,%3}, [%4];"
                    : "=r"(r0), "=r"(r1), "=r"(r2), "=r"(r3) : "r"(addr));
                bfr[ng * 2][0] = r0; bfr[ng * 2][1] = r1;
                bfr[ng * 2 + 1][0] = r2; bfr[ng * 2 + 1][1] = r3;
            }
#pragma unroll
            for (int mt = 0; mt < 2; mt++)
#pragma unroll
                for (int nt = 0; nt < 8; nt++) {
                    asm volatile(
                        "mma.sync.aligned.m16n8k16.row.col.f32.bf16.bf16.f32 "
                        "{%0,%1,%2,%3}, {%4,%5,%6,%7}, {%8,%9}, {%0,%1,%2,%3};"
                        : "+f"(c[mt][nt][0]), "+f"(c[mt][nt][1]),
                          "+f"(c[mt][nt][2]), "+f"(c[mt][nt][3])
                        : "r"(a[mt][0]), "r"(a[mt][1]), "r"(a[mt][2]), "r"(a[mt][3]),
                          "r"(bfr[nt][0]), "r"(bfr[nt][1]));
                }
        }
        __syncthreads();
    }

    // epilogue
    float* Cb; int cl0; const float* bias;
    if (blockIdx.x < 16) { Cb = Pg;       cl0 = n0;        bias = nullptr; }
    else                 { Cb = logits_t; cl0 = n0 - 2048; bias = out_b; }
#pragma unroll
    for (int mt = 0; mt < 2; mt++) {
        int r0g = m0 + wm * 32 + mt * 16 + (lane >> 2);
#pragma unroll
        for (int nt = 0; nt < 8; nt++) {
            int col = cl0 + wn * 64 + nt * 8 + (lane & 3) * 2;
            float b0 = bias ? bias[col] : 0.f;
            float b1 = bias ? bias[col + 1] : 0.f;
            float2 v0 = make_float2(c[mt][nt][0] + b0, c[mt][nt][1] + b1);
            float2 v1 = make_float2(c[mt][nt][2] + b0, c[mt][nt][3] + b1);
            *reinterpret_cast<float2*>(&Cb[(size_t)r0g * 2048 + col]) = v0;
            *reinterpret_cast<float2*>(&Cb[(size_t)(r0g + 8) * 2048 + col]) = v1;
        }
    }
}

// ============ prologue: transpose+split [w_hh | out_w] -> Wt0/1/2 [4096][512] ============
__global__ __launch_bounds__(256) void wtsplit_kernel(
    const float* __restrict__ w_hh, const float* __restrict__ out_w)
{
    __shared__ float tile[32][33];
    int n0 = blockIdx.x * 32;
    int k0 = blockIdx.y * 32;
    int tx = threadIdx.x & 31;
    int ty = threadIdx.x >> 5;   // 0..7
#pragma unroll
    for (int r = 0; r < 4; r++) {
        int k = k0 + ty + 8 * r;
        int n = n0 + tx;
        float v = (n < 2048) ? w_hh[(size_t)k * 2048 + n]
                             : out_w[(size_t)k * 2048 + (n - 2048)];
        tile[ty + 8 * r][tx] = v;
    }
    __syncthreads();
#pragma unroll
    for (int r = 0; r < 4; r++) {
        int nrel = ty + 8 * r;
        int krel = tx;
        float v = tile[krel][nrel];
        __nv_bfloat16 b0, b1, b2;
        split3(v, b0, b1, b2);
        size_t idx = (size_t)(n0 + nrel) * 512 + (k0 + krel);
        g_Wt0[idx] = b0; g_Wt1[idx] = b1; g_Wt2[idx] = b2;
    }
}

// ---------------- FFMA2 GEMM 128x128 (eproj) ----------------
#define BM 128
#define BN 128
#define BK 16
#define ASTRIDE 130
#define WSTRIDE 132
#define ASTR64 66
#define WSTR64 68

__global__ __launch_bounds__(256, 2) void gemm2_kernel(
    const float* __restrict__ A, int K,
    const float* __restrict__ W1, const float* __restrict__ b1a, const float* __restrict__ b1b,
    float* __restrict__ C1, int N1)
{
    __shared__ float As[2][BK][ASTRIDE];
    __shared__ float Ws[2][BK][WSTRIDE];

    const int tid = threadIdx.x;
    const int tx = tid & 15;
    const int ty = tid >> 4;
    const int row0 = blockIdx.y * BM;
    const int col0 = blockIdx.x * BN;

    const float* W = W1; const float* ba = b1a; const float* bb = b1b;
    float* C = C1; int ldN = N1; int cloc0 = col0;

    const int lrA  = tid >> 2;
    const int lkk4 = (tid & 3) * 4;
    const int lkkw = tid >> 4;
    const int lnn4 = (tid & 15) * 4;

    const float* Arow0 = A + (size_t)(row0 + lrA) * K + lkk4;
    const float* Arow1 = A + (size_t)(row0 + lrA + 64) * K + lkk4;
    const float* Wrow  = W + (size_t)lkkw * ldN + cloc0;

    unsigned long long acc[4][8];
#pragma unroll
    for (int p = 0; p < 4; p++)
#pragma unroll
        for (int j = 0; j < 8; j++) acc[p][j] = 0ull;

    const int KT = K / BK;
    float4 fa0, fa1, fw0, fw1;

    fa0 = *reinterpret_cast<const float4*>(Arow0);
    fa1 = *reinterpret_cast<const float4*>(Arow1);
    fw0 = *reinterpret_cast<const float4*>(Wrow + lnn4);
    fw1 = *reinterpret_cast<const float4*>(Wrow + 64 + lnn4);
    {
        float av0[4] = {fa0.x, fa0.y, fa0.z, fa0.w};
        float av1[4] = {fa1.x, fa1.y, fa1.z, fa1.w};
#pragma unroll
        for (int i = 0; i < 4; i++) {
            As[0][lkk4 + i][lrA] = av0[i];
            As[0][lkk4 + i][lrA + 64] = av1[i];
        }
        *reinterpret_cast<float4*>(&Ws[0][lkkw][lnn4]) = fw0;
        *reinterpret_cast<float4*>(&Ws[0][lkkw][64 + lnn4]) = fw1;
    }

    int buf = 0;
    for (int t = 0; t < KT; ++t) {
        __syncthreads();
        if (t + 1 < KT) {
            int k0 = (t + 1) * BK;
            fa0 = *reinterpret_cast<const float4*>(Arow0 + k0);
            fa1 = *reinterpret_cast<const float4*>(Arow1 + k0);
            fw0 = *reinterpret_cast<const float4*>(Wrow + (size_t)k0 * ldN + lnn4);
            fw1 = *reinterpret_cast<const float4*>(Wrow + (size_t)k0 * ldN + 64 + lnn4);
        }
#pragma unroll
        for (int kk = 0; kk < BK; ++kk) {
            const unsigned long long* ap0 =
                reinterpret_cast<const unsigned long long*>(&As[buf][kk][ty * 4]);
            const unsigned long long* ap1 =
                reinterpret_cast<const unsigned long long*>(&As[buf][kk][64 + ty * 4]);
            unsigned long long a01 = ap0[0];
            unsigned long long a23 = ap0[1];
            unsigned long long a45 = ap1[0];
            unsigned long long a67 = ap1[1];
            float4 w03 = *reinterpret_cast<const float4*>(&Ws[buf][kk][tx * 4]);
            float4 w47 = *reinterpret_cast<const float4*>(&Ws[buf][kk][64 + tx * 4]);
            unsigned long long wd[8];
            wd[0] = dup2(w03.x); wd[1] = dup2(w03.y); wd[2] = dup2(w03.z); wd[3] = dup2(w03.w);
            wd[4] = dup2(w47.x); wd[5] = dup2(w47.y); wd[6] = dup2(w47.z); wd[7] = dup2(w47.w);
#pragma unroll
            for (int j = 0; j < 8; j++) {
                ffma2(acc[0][j], a01, wd[j]);
                ffma2(acc[1][j], a23, wd[j]);
                ffma2(acc[2][j], a45, wd[j]);
                ffma2(acc[3][j], a67, wd[j]);
            }
        }
        if (t + 1 < KT) {
            int nb = buf ^ 1;
            float av0[4] = {fa0.x, fa0.y, fa0.z, fa0.w};
            float av1[4] = {fa1.x, fa1.y, fa1.z, fa1.w};
#pragma unroll
            for (int i = 0; i < 4; i++) {
                As[nb][lkk4 + i][lrA] = av0[i];
                As[nb][lkk4 + i][lrA + 64] = av1[i];
            }
            *reinterpret_cast<float4*>(&Ws[nb][lkkw][lnn4]) = fw0;
            *reinterpret_cast<float4*>(&Ws[nb][lkkw][64 + lnn4]) = fw1;
        }
        buf ^= 1;
    }

    float bv[2][4];
#pragma unroll
    for (int g = 0; g < 2; g++) {
        int cb = cloc0 + g * 64 + tx * 4;
#pragma unroll
        for (int jj = 0; jj < 4; jj++) {
            float v = 0.f;
            if (ba) v += ba[cb + jj];
            if (bb) v += bb[cb + jj];
            bv[g][jj] = v;
        }
    }
#pragma unroll
    for (int hh = 0; hh < 2; hh++) {
#pragma unroll
        for (int pp = 0; pp < 2; pp++) {
            int p = hh * 2 + pp;
            float2 f[8];
#pragma unroll
            for (int j = 0; j < 8; j++) f[j] = unpack2(acc[p][j]);
            int rbase = row0 + hh * 64 + ty * 4 + 2 * pp;
#pragma unroll
            for (int lane = 0; lane < 2; lane++) {
                int r = rbase + lane;
#pragma unroll
                for (int g = 0; g < 2; g++) {
                    int cc = cloc0 + g * 64 + tx * 4;
                    float4 o;
                    o.x = (lane ? f[g * 4 + 0].y : f[g * 4 + 0].x) + bv[g][0];
                    o.y = (lane ? f[g * 4 + 1].y : f[g * 4 + 1].x) + bv[g][1];
                    o.z = (lane ? f[g * 4 + 2].y : f[g * 4 + 2].x) + bv[g][2];
                    o.w = (lane ? f[g * 4 + 3].y : f[g * 4 + 3].x) + bv[g][3];
                    *reinterpret_cast<float4*>(&C[(size_t)r * ldN + cc]) = o;
                }
            }
        }
    }
}

// ---------------- FFMA2 GEMM 64x128 (Pg0 prologue only) ----------------
__global__ __launch_bounds__(256, 2) void gemmS_kernel(
    const float* __restrict__ A, int K,
    const float* __restrict__ W1, float* __restrict__ C1, int N1)
{
    __shared__ float As[2][BK][ASTR64];
    __shared__ float Ws[2][BK][WSTRIDE];

    const int tid = threadIdx.x;
    const int tx = tid & 15;
    const int ty = tid >> 4;
    const int row0 = blockIdx.y * 64;
    const int col0 = blockIdx.x * BN;

    const int lrA  = tid >> 2;
    const int lkk4 = (tid & 3) * 4;
    const int lkkw = tid >> 4;
    const int lnn4 = (tid & 15) * 4;

    const float* Arow = A + (size_t)(row0 + lrA) * K + lkk4;
    const float* Wrow = W1 + (size_t)lkkw * N1 + col0;

    unsigned long long acc[2][8];
#pragma unroll
    for (int p = 0; p < 2; p++)
#pragma unroll
        for (int j = 0; j < 8; j++) acc[p][j] = 0ull;

    const int KT = K / BK;
    float4 fa, fw0, fw1;

    fa  = *reinterpret_cast<const float4*>(Arow);
    fw0 = *reinterpret_cast<const float4*>(Wrow + lnn4);
    fw1 = *reinterpret_cast<const float4*>(Wrow + 64 + lnn4);
    {
        float av[4] = {fa.x, fa.y, fa.z, fa.w};
#pragma unroll
        for (int i = 0; i < 4; i++) As[0][lkk4 + i][lrA] = av[i];
        *reinterpret_cast<float4*>(&Ws[0][lkkw][lnn4]) = fw0;
        *reinterpret_cast<float4*>(&Ws[0][lkkw][64 + lnn4]) = fw1;
    }

    int buf = 0;
    for (int t = 0; t < KT; ++t) {
        __syncthreads();
        if (t + 1 < KT) {
            int k0 = (t + 1) * BK;
            fa  = *reinterpret_cast<const float4*>(Arow + k0);
            fw0 = *reinterpret_cast<const float4*>(Wrow + (size_t)k0 * N1 + lnn4);
            fw1 = *reinterpret_cast<const float4*>(Wrow + (size_t)k0 * N1 + 64 + lnn4);
        }
#pragma unroll
        for (int kk = 0; kk < BK; ++kk) {
            const unsigned long long* ap =
                reinterpret_cast<const unsigned long long*>(&As[buf][kk][ty * 4]);
            unsigned long long a01 = ap[0];
            unsigned long long a23 = ap[1];
            float4 w03 = *reinterpret_cast<const float4*>(&Ws[buf][kk][tx * 4]);
            float4 w47 = *reinterpret_cast<const float4*>(&Ws[buf][kk][64 + tx * 4]);
            unsigned long long wd[8];
            wd[0] = dup2(w03.x); wd[1] = dup2(w03.y); wd[2] = dup2(w03.z); wd[3] = dup2(w03.w);
            wd[4] = dup2(w47.x); wd[5] = dup2(w47.y); wd[6] = dup2(w47.z); wd[7] = dup2(w47.w);
#pragma unroll
            for (int j = 0; j < 8; j++) {
                ffma2(acc[0][j], a01, wd[j]);
                ffma2(acc[1][j], a23, wd[j]);
            }
        }
        if (t + 1 < KT) {
            int nb = buf ^ 1;
            float av[4] = {fa.x, fa.y, fa.z, fa.w};
#pragma unroll
            for (int i = 0; i < 4; i++) As[nb][lkk4 + i][lrA] = av[i];
            *reinterpret_cast<float4*>(&Ws[nb][lkkw][lnn4]) = fw0;
            *reinterpret_cast<float4*>(&Ws[nb][lkkw][64 + lnn4]) = fw1;
        }
        buf ^= 1;
    }

#pragma unroll
    for (int p = 0; p < 2; p++) {
        float2 f[8];
#pragma unroll
        for (int j = 0; j < 8; j++) f[j] = unpack2(acc[p][j]);
        int rbase = row0 + ty * 4 + 2 * p;
#pragma unroll
        for (int lane = 0; lane < 2; lane++) {
            int r = rbase + lane;
#pragma unroll
            for (int g = 0; g < 2; g++) {
                int cc = col0 + g * 64 + tx * 4;
                float4 o;
                o.x = (lane ? f[g * 4 + 0].y : f[g * 4 + 0].x);
                o.y = (lane ? f[g * 4 + 1].y : f[g * 4 + 1].x);
                o.z = (lane ? f[g * 4 + 2].y : f[g * 4 + 2].x);
                o.w = (lane ? f[g * 4 + 3].y : f[g * 4 + 3].x);
                *reinterpret_cast<float4*>(&C1[(size_t)r * N1 + cc]) = o;
            }
        }
    }
}

// ---------------- 64x64-tile GEMM (h0 prologue) ----------------
__global__ __launch_bounds__(256, 2) void gemm64_kernel(
    const float* __restrict__ A, int K,
    const float* __restrict__ W, const float* __restrict__ bias,
    float* __restrict__ C, int N)
{
    __shared__ float As[2][BK][ASTR64];
    __shared__ float Ws[2][BK][WSTR64];

    const int tid = threadIdx.x;
    const int tx = tid & 15;
    const int ty = tid >> 4;
    const int row0 = blockIdx.y * 64;
    const int col0 = blockIdx.x * 64;

    const int lrA  = tid >> 2;
    const int lkk4 = (tid & 3) * 4;
    const int lkkw = tid >> 4;
    const int lnn4 = (tid & 15) * 4;

    const float* Arow = A + (size_t)(row0 + lrA) * K + lkk4;
    const float* Wrow = W + (size_t)lkkw * N + col0 + lnn4;

    unsigned long long acc[2][4];
#pragma unroll
    for (int p = 0; p < 2; p++)
#pragma unroll
        for (int j = 0; j < 4; j++) acc[p][j] = 0ull;

    const int KT = K / BK;
    float4 fa, fw;

    fa = *reinterpret_cast<const float4*>(Arow);
    fw = *reinterpret_cast<const float4*>(Wrow);
    {
        float av[4] = {fa.x, fa.y, fa.z, fa.w};
#pragma unroll
        for (int i = 0; i < 4; i++) As[0][lkk4 + i][lrA] = av[i];
        *reinterpret_cast<float4*>(&Ws[0][lkkw][lnn4]) = fw;
    }

    int buf = 0;
    for (int t = 0; t < KT; ++t) {
        __syncthreads();
        if (t + 1 < KT) {
            int k0 = (t + 1) * BK;
            fa = *reinterpret_cast<const float4*>(Arow + k0);
            fw = *reinterpret_cast<const float4*>(Wrow + (size_t)k0 * N);
        }
#pragma unroll
        for (int kk = 0; kk < BK; ++kk) {
            const unsigned long long* ap =
                reinterpret_cast<const unsigned long long*>(&As[buf][kk][ty * 4]);
            unsigned long long a01 = ap[0];
            unsigned long long a23 = ap[1];
            float4 w4 = *reinterpret_cast<const float4*>(&Ws[buf][kk][tx * 4]);
            unsigned long long wd[4];
            wd[0] = dup2(w4.x); wd[1] = dup2(w4.y); wd[2] = dup2(w4.z); wd[3] = dup2(w4.w);
#pragma unroll
            for (int j = 0; j < 4; j++) {
                ffma2(acc[0][j], a01, wd[j]);
                ffma2(acc[1][j], a23, wd[j]);
            }
        }
        if (t + 1 < KT) {
            int nb = buf ^ 1;
            float av[4] = {fa.x, fa.y, fa.z, fa.w};
#pragma unroll
            for (int i = 0; i < 4; i++) As[nb][lkk4 + i][lrA] = av[i];
            *reinterpret_cast<float4*>(&Ws[nb][lkkw][lnn4]) = fw;
        }
        buf ^= 1;
    }

    float bvv[4];
#pragma unroll
    for (int jj = 0; jj < 4; jj++)
        bvv[jj] = bias ? bias[col0 + tx * 4 + jj] : 0.f;
#pragma unroll
    for (int p = 0; p < 2; p++) {
        float2 f[4];
#pragma unroll
        for (int j = 0; j < 4; j++) f[j] = unpack2(acc[p][j]);
        int rbase = row0 + ty * 4 + 2 * p;
        int cc = col0 + tx * 4;
#pragma unroll
        for (int lane = 0; lane < 2; lane++) {
            float4 o;
            o.x = (lane ? f[0].y : f[0].x) + bvv[0];
            o.y = (lane ? f[1].y : f[1].x) + bvv[1];
            o.z = (lane ? f[2].y : f[2].x) + bvv[2];
            o.w = (lane ? f[3].y : f[3].x) + bvv[3];
            *reinterpret_cast<float4*>(&C[(size_t)(rbase + lane) * N + cc]) = o;
        }
    }
}

// ---------------- sos projection ----------------
__global__ __launch_bounds__(256) void sosproj_kernel(
    const float* __restrict__ sos, const float* __restrict__ w_ih,
    const float* __restrict__ b_ih, const float* __restrict__ b_hh) {
    __shared__ float part[4][64];
    int c = blockIdx.x * 64 + (threadIdx.x & 63);
    int seg = threadIdx.x >> 6;
    float acc = 0.f;
    for (int k = seg * 128; k < seg * 128 + 128; ++k)
        acc = fmaf(__ldg(&sos[k]), w_ih[(size_t)k * G4H + c], acc);
    part[seg][threadIdx.x & 63] = acc;
    __syncthreads();
    if (threadIdx.x < 64) {
        int cc = blockIdx.x * 64 + threadIdx.x;
        float s = part[0][threadIdx.x] + part[1][threadIdx.x] +
                  part[2][threadIdx.x] + part[3][threadIdx.x];
        g_sosproj[cc] = s + b_ih[cc] + b_hh[cc];
    }
}

// ---------------- init: c = 0 ----------------
__global__ void init_kernel() {
    int idx = blockIdx.x * blockDim.x + threadIdx.x;
    if (idx < B * H) g_c[idx] = 0.f;
}

// ---------------- standalone LSTM (t = 0) + bf16x3 split ----------------
__global__ __launch_bounds__(256) void lstm0_kernel() {
    int idx = blockIdx.x * blockDim.x + threadIdx.x;
    if (idx >= B * H / 2) return;
    int b = idx >> 8;
    int j = (idx & 255) * 2;
    const float* pr = g_Pg + (size_t)b * G4H;
    const float* ep = g_sosproj;
    float2 pi = *reinterpret_cast<const float2*>(pr + j);
    float2 pf = *reinterpret_cast<const float2*>(pr + H + j);
    float2 pg = *reinterpret_cast<const float2*>(pr + 2 * H + j);
    float2 po = *reinterpret_cast<const float2*>(pr + 3 * H + j);
    float2 ei = *reinterpret_cast<const float2*>(ep + j);
    float2 ef = *reinterpret_cast<const float2*>(ep + H + j);
    float2 eg = *reinterpret_cast<const float2*>(ep + 2 * H + j);
    float2 eo = *reinterpret_cast<const float2*>(ep + 3 * H + j);
    float2 cv = *reinterpret_cast<const float2*>(g_c + (size_t)b * H + j);
    float2 hn, cn;
    {
        float ig = sigmoidf_(pi.x + ei.x), fg = sigmoidf_(pf.x + ef.x);
        float gg = tanhf(pg.x + eg.x),     og = sigmoidf_(po.x + eo.x);
        cn.x = fg * cv.x + ig * gg; hn.x = og * tanhf(cn.x);
    }
    {
        float ig = sigmoidf_(pi.y + ei.y), fg = sigmoidf_(pf.y + ef.y);
        float gg = tanhf(pg.y + eg.y),     og = sigmoidf_(po.y + eo.y);
        cn.y = fg * cv.y + ig * gg; hn.y = og * tanhf(cn.y);
    }
    *reinterpret_cast<float2*>(g_c + (size_t)b * H + j) = cn;
    *reinterpret_cast<float2*>(g_h + (size_t)b * H + j) = hn;
    __nv_bfloat16 x0, x1, x2, y0, y1, y2;
    split3(hn.x, x0, x1, x2);
    split3(hn.y, y0, y1, y2);
    size_t o = (size_t)b * H + j;
    *reinterpret_cast<__nv_bfloat162*>(g_A0 + o) = __nv_bfloat162(x0, y0);
    *reinterpret_cast<__nv_bfloat162*>(g_A1 + o) = __nv_bfloat162(x1, y1);
    *reinterpret_cast<__nv_bfloat162*>(g_A2 + o) = __nv_bfloat162(x2, y2);
}

// ------- sampleA: max/lse/argmax + seq/logp + fused LSTM + bf16x3 split -------
__global__ __launch_bounds__(256) void sampleA_kernel(
    float* __restrict__ o_seq, float* __restrict__ o_logp,
    uint32_t sk0, uint32_t sk1, int t)
{
    __shared__ float sred[256];
    __shared__ int   sredi[256];
    __shared__ float s_rowmax, s_lse;
    __shared__ int   s_sym;

    int b = blockIdx.x;
    int tid = threadIdx.x;
    const float* lr = g_logits + (size_t)(t & 1) * B * V + (size_t)b * V;

    float lv[8];
#pragma unroll
    for (int i = 0; i < 8; i++) lv[i] = lr[tid + 256 * i];

    float m = -3.402823466e38f;
#pragma unroll
    for (int i = 0; i < 8; i++) m = fmaxf(m, lv[i]);
    sred[tid] = m; __syncthreads();
    for (int s = 128; s > 0; s >>= 1) {
        if (tid < s) sred[tid] = fmaxf(sred[tid], sred[tid + s]);
        __syncthreads();
    }
    if (tid == 0) s_rowmax = sred[0];
    __syncthreads();
    float rowmax = s_rowmax;

    float sum = 0.f;
#pragma unroll
    for (int i = 0; i < 8; i++) sum += expf(lv[i] - rowmax);
    sred[tid] = sum; __syncthreads();
    for (int s = 128; s > 0; s >>= 1) {
        if (tid < s) sred[tid] += sred[tid + s];
        __syncthreads();
    }
    if (tid == 0) s_lse = logf(sred[0]);
    __syncthreads();
    float lse = s_lse;

    float best = -3.402823466e38f;
    int bestv = V;
    const float TINY = 1.17549435e-38f;
#pragma unroll
    for (int i = 0; i < 8; i++) {
        int v = tid + 256 * i;
        float lsm = lv[i] - rowmax - lse;
        uint32_t o0, o1;
        threefry2x32(sk0, sk1, 0u, (uint32_t)(b * V + v), o0, o1);
        uint32_t bits = o0 ^ o1;
        float uf = __uint_as_float(0x3f800000u | (bits >> 9)) - 1.0f;
        float u = fmaxf(TINY, uf + TINY);
        float g = -logf(-logf(u));
        float sc = lsm + g;
        if (sc > best) { best = sc; bestv = v; }
    }

    sred[tid] = best; sredi[tid] = bestv; __syncthreads();
    for (int s = 128; s > 0; s >>= 1) {
        if (tid < s) {
            float ov = sred[tid + s]; int oi = sredi[tid + s];
            if (ov > sred[tid] || (ov == sred[tid] && oi < sredi[tid])) {
                sred[tid] = ov; sredi[tid] = oi;
            }
        }
        __syncthreads();
    }
    if (tid == 0) {
        int sym = sredi[0];
        s_sym = sym;
        o_seq[b * L + t] = (float)sym;
        o_logp[b * L + t] = lr[sym] - rowmax - lse;
        g_mls[(t & 1) * B + b] = make_float2(rowmax, lse);
    }
    if (t >= MAX_LEN - 1) return;

    __syncthreads();
    int sym = s_sym;

    int j = tid * 2;
    const float* pr = g_Pg + (size_t)b * G4H;
    const float* ep = g_eproj + (size_t)sym * G4H;
    float2 pi = *reinterpret_cast<const float2*>(pr + j);
    float2 pf = *reinterpret_cast<const float2*>(pr + H + j);
    float2 pg = *reinterpret_cast<const float2*>(pr + 2 * H + j);
    float2 po = *reinterpret_cast<const float2*>(pr + 3 * H + j);
    float2 ei = *reinterpret_cast<const float2*>(ep + j);
    float2 ef = *reinterpret_cast<const float2*>(ep + H + j);
    float2 eg = *reinterpret_cast<const float2*>(ep + 2 * H + j);
    float2 eo = *reinterpret_cast<const float2*>(ep + 3 * H + j);
    float2 cv = *reinterpret_cast<const float2*>(g_c + (size_t)b * H + j);
    float2 hn, cn;
    {
        float ig = sigmoidf_(pi.x + ei.x), fg = sigmoidf_(pf.x + ef.x);
        float gg = tanhf(pg.x + eg.x),     og = sigmoidf_(po.x + eo.x);
        cn.x = fg * cv.x + ig * gg; hn.x = og * tanhf(cn.x);
    }
    {
        float ig = sigmoidf_(pi.y + ei.y), fg = sigmoidf_(pf.y + ef.y);
        float gg = tanhf(pg.y + eg.y),     og = sigmoidf_(po.y + eo.y);
        cn.y = fg * cv.y + ig * gg; hn.y = og * tanhf(cn.y);
    }
    *reinterpret_cast<float2*>(g_c + (size_t)b * H + j) = cn;
    *reinterpret_cast<float2*>(g_h + (size_t)b * H + j) = hn;
    __nv_bfloat16 x0, x1, x2, y0, y1, y2;
    split3(hn.x, x0, x1, x2);
    split3(hn.y, y0, y1, y2);
    size_t o = (size_t)b * H + j;
    *reinterpret_cast<__nv_bfloat162*>(g_A0 + o) = __nv_bfloat162(x0, y0);
    *reinterpret_cast<__nv_bfloat162*>(g_A1 + o) = __nv_bfloat162(x1, y1);
    *reinterpret_cast<__nv_bfloat162*>(g_A2 + o) = __nv_bfloat162(x2, y2);
}

// ------- sampleB (side stream): probs + entropy -------
__global__ __launch_bounds__(256) void sampleB_kernel(
    float* __restrict__ o_probs, float* __restrict__ o_ent, int t)
{
    __shared__ float sred[256];
    int b = blockIdx.x;
    int tid = threadIdx.x;
    const float* lr = g_logits + (size_t)(t & 1) * B * V + (size_t)b * V;
    float2 ml = g_mls[(t & 1) * B + b];
    float rowmax = ml.x, lse = ml.y;

    float entacc = 0.f;
    size_t pbase = ((size_t)b * L + t) * V;
    for (int v = tid; v < V; v += 256) {
        float lsm = lr[v] - rowmax - lse;
        float p = expf(lsm);
        o_probs[pbase + v] = p;
        entacc += p * lsm;
    }
    sred[tid] = entacc; __syncthreads();
    for (int s = 128; s > 0; s >>= 1) {
        if (tid < s) sred[tid] += sred[tid + s];
        __syncthreads();
    }
    if (tid == 0) o_ent[b * L + t] = -sred[0];
}

// ---------------- EOS step ----------------
__global__ void eos_kernel(float* __restrict__ o_seq, float* __restrict__ o_probs,
                           float* __restrict__ o_logp, float* __restrict__ o_ent) {
    int idx = blockIdx.x * blockDim.x + threadIdx.x;
    if (idx < B * V) {
        int b = idx / V, v = idx % V;
        o_probs[((size_t)b * L + MAX_LEN) * V + v] = 1.0f;
    }
    if (idx < B) {
        o_seq[idx * L + MAX_LEN]  = 0.f;
        o_logp[idx * L + MAX_LEN] = 0.f;
        o_ent[idx * L + MAX_LEN]  = 0.f;
    }
}

// ---------------- launch ----------------
extern "C" void kernel_launch(void* const* d_in, const int* in_sizes, int n_in,
                              void* d_out, int out_size) {
    const float* x         = (const float*)d_in[0];
    const float* agent_w   = (const float*)d_in[1];
    const float* agent_b   = (const float*)d_in[2];
    const float* sos       = (const float*)d_in[3];
    const float* embedding = (const float*)d_in[4];
    const float* w_ih      = (const float*)d_in[5];
    const float* w_hh      = (const float*)d_in[6];
    const float* b_ih      = (const float*)d_in[7];
    const float* b_hh      = (const float*)d_in[8];
    const float* out_w     = (const float*)d_in[9];
    const float* out_b     = (const float*)d_in[10];

    float* out = (float*)d_out;
    float* o_seq   = out;
    float* o_probs = out + (size_t)B * L;
    float* o_logp  = o_probs + (size_t)B * L * V;
    float* o_ent   = o_logp + (size_t)B * L;

    static float *dh = nullptr, *dPg = nullptr, *dl = nullptr, *dep = nullptr;
    static cudaStream_t s2;
    static cudaEvent_t e0, e1, evA, evB[2];
    if (!dh) {
        cudaGetSymbolAddress((void**)&dh, g_h);
        cudaGetSymbolAddress((void**)&dPg, g_Pg);
        cudaGetSymbolAddress((void**)&dl, g_logits);
        cudaGetSymbolAddress((void**)&dep, g_eproj);
        cudaStreamCreateWithFlags(&s2, cudaStreamNonBlocking);
        cudaEventCreateWithFlags(&e0, cudaEventDisableTiming);
        cudaEventCreateWithFlags(&e1, cudaEventDisableTiming);
        cudaEventCreateWithFlags(&evA, cudaEventDisableTiming);
        cudaEventCreateWithFlags(&evB[0], cudaEventDisableTiming);
        cudaEventCreateWithFlags(&evB[1], cudaEventDisableTiming);
    }

    init_kernel<<<(B * H + 255) / 256, 256>>>();
    cudaEventRecord(e0, 0);

    // side stream: emb_proj
    cudaStreamWaitEvent(s2, e0, 0);
    gemm2_kernel<<<dim3(G4H / BN, V / BM), 256, 0, s2>>>(
        embedding, E_DIM, w_ih, b_ih, b_hh, dep, G4H);
    cudaEventRecord(e1, s2);

    // main stream prologue
    sosproj_kernel<<<32, 256>>>(sos, w_ih, b_ih, b_hh);
    wtsplit_kernel<<<dim3(128, 16), 256>>>(w_hh, out_w);
    gemm64_kernel<<<dim3(H / 64, B / 64), 256>>>(x, IN_DIM, agent_w, agent_b, dh, H);
    gemmS_kernel<<<dim3(G4H / BN, B / 64), 256>>>(dh, H, w_hh, dPg, G4H);
    lstm0_kernel<<<(B * H / 2 + 255) / 256, 256>>>();

    uint32_t k0 = 0u, k1 = 1u;
    for (int t = 0; t < MAX_LEN; ++t) {
        uint32_t n0, n1, s0cap, s1cap;
        threefry2x32(k0, k1, 0u, 0u, n0, n1);
        threefry2x32(k0, k1, 0u, 1u, s0cap, s1cap);

        float* dlt = dl + (size_t)(t & 1) * B * V;

        if (t >= 2) cudaStreamWaitEvent(0, evB[t & 1], 0);

        // HMMA tensor-core: Pg(next) = h@w_hh ; logits = h@out_w + out_b
        gemmMMA_kernel<<<dim3(32, 4), 256, MM_SMEM>>>(dPg, dlt, out_b);

        if (t == 0) cudaStreamWaitEvent(0, e1, 0);

        sampleA_kernel<<<B, 256>>>(o_seq, o_logp, s0cap, s1cap, t);
        cudaEventRecord(evA, 0);

        cudaStreamWaitEvent(s2, evA, 0);
        sampleB_kernel<<<B, 256, 0, s2>>>(o_probs, o_ent, t);
        cudaEventRecord(evB[t & 1], s2);

        k0 = n0; k1 = n1;
    }

    cudaStreamWaitEvent(0, evB[0], 0);
    cudaStreamWaitEvent(0, evB[1], 0);
    eos_kernel<<<(B * V + 255) / 256, 256>>>(o_seq, o_probs, o_logp, o_ent);
}

// round 13
// speedup vs baseline: 1.2777x; 1.2777x over previous
#include <cuda_runtime.h>
#include <cstdint>
#include <math.h>

#define B 512
#define IN_DIM 1024
#define H 512
#define E_DIM 512
#define V 2048
#define MAX_LEN 32
#define L 33
#define G4H (4 * H)

// ---------------- scratch (no allocations allowed) ----------------
__device__ float g_h[B * H];
__device__ float g_c[B * H];
__device__ float g_Pg[(size_t)B * G4H];          // h @ w_hh partial gates
__device__ float g_logits[(size_t)2 * B * V];    // double-buffered by t parity
__device__ float2 g_mls[2 * B];                  // (rowmax, lse) per row, by parity
__device__ float g_eproj[(size_t)V * G4H];       // embedding @ w_ih + b_ih + b_hh
__device__ float g_sosproj[G4H];                 // sos @ w_ih + b_ih + b_hh

// ---------------- threefry2x32 (JAX-compatible, 20 rounds) ----------------
__host__ __device__ __forceinline__ uint32_t rotl32(uint32_t v, int d) {
    return (v << d) | (v >> (32 - d));
}

__host__ __device__ __forceinline__ void threefry2x32(uint32_t k0, uint32_t k1,
                                                      uint32_t x0, uint32_t x1,
                                                      uint32_t& o0, uint32_t& o1) {
    uint32_t ks2 = k0 ^ k1 ^ 0x1BD11BDAu;
    x0 += k0; x1 += k1;
#define TF_R(r) { x0 += x1; x1 = rotl32(x1, r); x1 ^= x0; }
    TF_R(13) TF_R(15) TF_R(26) TF_R(6)
    x0 += k1; x1 += ks2 + 1u;
    TF_R(17) TF_R(29) TF_R(16) TF_R(24)
    x0 += ks2; x1 += k0 + 2u;
    TF_R(13) TF_R(15) TF_R(26) TF_R(6)
    x0 += k0; x1 += k1 + 3u;
    TF_R(17) TF_R(29) TF_R(16) TF_R(24)
    x0 += k1; x1 += ks2 + 4u;
    TF_R(13) TF_R(15) TF_R(26) TF_R(6)
    x0 += ks2; x1 += k0 + 5u;
#undef TF_R
    o0 = x0; o1 = x1;
}

__device__ __forceinline__ float sigmoidf_(float x) {
    // XLA logistic expansion: 0.5 + 0.5 * tanh(0.5 * x)
    return 0.5f + 0.5f * tanhf(0.5f * x);
}

// ---------------- packed f32x2 helpers ----------------
__device__ __forceinline__ void ffma2(unsigned long long& acc, unsigned long long a,
                                      unsigned long long b) {
    asm("fma.rn.f32x2 %0, %1, %2, %0;" : "+l"(acc) : "l"(a), "l"(b));
}
__device__ __forceinline__ unsigned long long dup2(float w) {
    unsigned long long r;
    asm("mov.b64 %0, {%1, %1};" : "=l"(r) : "r"(__float_as_uint(w)));
    return r;
}
__device__ __forceinline__ float2 unpack2(unsigned long long v) {
    float2 f;
    asm("mov.b64 {%0, %1}, %2;" : "=f"(f.x), "=f"(f.y) : "l"(v));
    return f;
}

// ---------------- FFMA2 GEMM 128x128 (r2 config): dual-output split columns ----
#define BM 128
#define BN 128
#define BK 16
#define ASTRIDE 130
#define WSTRIDE 132
#define ASTR64 66
#define WSTR64 68

__global__ __launch_bounds__(256, 2) void gemm2_kernel(
    const float* __restrict__ A, int K,
    const float* __restrict__ W1, const float* __restrict__ b1a, const float* __restrict__ b1b,
    float* __restrict__ C1, int N1,
    const float* __restrict__ W2, const float* __restrict__ b2a,
    float* __restrict__ C2, int N2, int col_base)
{
    __shared__ float As[2][BK][ASTRIDE];
    __shared__ float Ws[2][BK][WSTRIDE];

    const int tid = threadIdx.x;
    const int tx = tid & 15;
    const int ty = tid >> 4;
    const int row0 = blockIdx.y * BM;
    const int col0 = blockIdx.x * BN + col_base;

    const float* W; const float* ba; const float* bb; float* C; int ldN; int cloc0;
    if (col0 < N1) { W = W1; ba = b1a; bb = b1b; C = C1; ldN = N1; cloc0 = col0; }
    else           { W = W2; ba = b2a; bb = nullptr; C = C2; ldN = N2; cloc0 = col0 - N1; }

    const int lrA  = tid >> 2;
    const int lkk4 = (tid & 3) * 4;
    const int lkkw = tid >> 4;
    const int lnn4 = (tid & 15) * 4;

    const float* Arow0 = A + (size_t)(row0 + lrA) * K + lkk4;
    const float* Arow1 = A + (size_t)(row0 + lrA + 64) * K + lkk4;
    const float* Wrow  = W + (size_t)lkkw * ldN + cloc0;

    unsigned long long acc[4][8];
#pragma unroll
    for (int p = 0; p < 4; p++)
#pragma unroll
        for (int j = 0; j < 8; j++) acc[p][j] = 0ull;

    const int KT = K / BK;
    float4 fa0, fa1, fw0, fw1;

    fa0 = *reinterpret_cast<const float4*>(Arow0);
    fa1 = *reinterpret_cast<const float4*>(Arow1);
    fw0 = *reinterpret_cast<const float4*>(Wrow + lnn4);
    fw1 = *reinterpret_cast<const float4*>(Wrow + 64 + lnn4);
    {
        float av0[4] = {fa0.x, fa0.y, fa0.z, fa0.w};
        float av1[4] = {fa1.x, fa1.y, fa1.z, fa1.w};
#pragma unroll
        for (int i = 0; i < 4; i++) {
            As[0][lkk4 + i][lrA] = av0[i];
            As[0][lkk4 + i][lrA + 64] = av1[i];
        }
        *reinterpret_cast<float4*>(&Ws[0][lkkw][lnn4]) = fw0;
        *reinterpret_cast<float4*>(&Ws[0][lkkw][64 + lnn4]) = fw1;
    }

    int buf = 0;
    for (int t = 0; t < KT; ++t) {
        __syncthreads();
        if (t + 1 < KT) {
            int k0 = (t + 1) * BK;
            fa0 = *reinterpret_cast<const float4*>(Arow0 + k0);
            fa1 = *reinterpret_cast<const float4*>(Arow1 + k0);
            fw0 = *reinterpret_cast<const float4*>(Wrow + (size_t)k0 * ldN + lnn4);
            fw1 = *reinterpret_cast<const float4*>(Wrow + (size_t)k0 * ldN + 64 + lnn4);
        }

#pragma unroll
        for (int kk = 0; kk < BK; ++kk) {
            const unsigned long long* ap0 =
                reinterpret_cast<const unsigned long long*>(&As[buf][kk][ty * 4]);
            const unsigned long long* ap1 =
                reinterpret_cast<const unsigned long long*>(&As[buf][kk][64 + ty * 4]);
            unsigned long long a01 = ap0[0];
            unsigned long long a23 = ap0[1];
            unsigned long long a45 = ap1[0];
            unsigned long long a67 = ap1[1];
            float4 w03 = *reinterpret_cast<const float4*>(&Ws[buf][kk][tx * 4]);
            float4 w47 = *reinterpret_cast<const float4*>(&Ws[buf][kk][64 + tx * 4]);
            unsigned long long wd[8];
            wd[0] = dup2(w03.x); wd[1] = dup2(w03.y); wd[2] = dup2(w03.z); wd[3] = dup2(w03.w);
            wd[4] = dup2(w47.x); wd[5] = dup2(w47.y); wd[6] = dup2(w47.z); wd[7] = dup2(w47.w);
#pragma unroll
            for (int j = 0; j < 8; j++) {
                ffma2(acc[0][j], a01, wd[j]);
                ffma2(acc[1][j], a23, wd[j]);
                ffma2(acc[2][j], a45, wd[j]);
                ffma2(acc[3][j], a67, wd[j]);
            }
        }

        if (t + 1 < KT) {
            int nb = buf ^ 1;
            float av0[4] = {fa0.x, fa0.y, fa0.z, fa0.w};
            float av1[4] = {fa1.x, fa1.y, fa1.z, fa1.w};
#pragma unroll
            for (int i = 0; i < 4; i++) {
                As[nb][lkk4 + i][lrA] = av0[i];
                As[nb][lkk4 + i][lrA + 64] = av1[i];
            }
            *reinterpret_cast<float4*>(&Ws[nb][lkkw][lnn4]) = fw0;
            *reinterpret_cast<float4*>(&Ws[nb][lkkw][64 + lnn4]) = fw1;
        }
        buf ^= 1;
    }

    float bv[2][4];
#pragma unroll
    for (int g = 0; g < 2; g++) {
        int cb = cloc0 + g * 64 + tx * 4;
#pragma unroll
        for (int jj = 0; jj < 4; jj++) {
            float v = 0.f;
            if (ba) v += ba[cb + jj];
            if (bb) v += bb[cb + jj];
            bv[g][jj] = v;
        }
    }
#pragma unroll
    for (int hh = 0; hh < 2; hh++) {
#pragma unroll
        for (int pp = 0; pp < 2; pp++) {
            int p = hh * 2 + pp;
            float2 f[8];
#pragma unroll
            for (int j = 0; j < 8; j++) f[j] = unpack2(acc[p][j]);
            int rbase = row0 + hh * 64 + ty * 4 + 2 * pp;
#pragma unroll
            for (int lane = 0; lane < 2; lane++) {
                int r = rbase + lane;
#pragma unroll
                for (int g = 0; g < 2; g++) {
                    int c = cloc0 + g * 64 + tx * 4;
                    float4 o;
                    o.x = (lane ? f[g * 4 + 0].y : f[g * 4 + 0].x) + bv[g][0];
                    o.y = (lane ? f[g * 4 + 1].y : f[g * 4 + 1].x) + bv[g][1];
                    o.z = (lane ? f[g * 4 + 2].y : f[g * 4 + 2].x) + bv[g][2];
                    o.w = (lane ? f[g * 4 + 3].y : f[g * 4 + 3].x) + bv[g][3];
                    *reinterpret_cast<float4*>(&C[(size_t)r * ldN + c]) = o;
                }
            }
        }
    }
}

// ---------------- 64x64-tile GEMM (h0 prologue) ----------------
__global__ __launch_bounds__(256, 2) void gemm64_kernel(
    const float* __restrict__ A, int K,
    const float* __restrict__ W, const float* __restrict__ bias,
    float* __restrict__ C, int N)
{
    __shared__ float As[2][BK][ASTR64];
    __shared__ float Ws[2][BK][WSTR64];

    const int tid = threadIdx.x;
    const int tx = tid & 15;
    const int ty = tid >> 4;
    const int row0 = blockIdx.y * 64;
    const int col0 = blockIdx.x * 64;

    const int lrA  = tid >> 2;
    const int lkk4 = (tid & 3) * 4;
    const int lkkw = tid >> 4;
    const int lnn4 = (tid & 15) * 4;

    const float* Arow = A + (size_t)(row0 + lrA) * K + lkk4;
    const float* Wrow = W + (size_t)lkkw * N + col0 + lnn4;

    unsigned long long acc[2][4];
#pragma unroll
    for (int p = 0; p < 2; p++)
#pragma unroll
        for (int j = 0; j < 4; j++) acc[p][j] = 0ull;

    const int KT = K / BK;
    float4 fa, fw;

    fa = *reinterpret_cast<const float4*>(Arow);
    fw = *reinterpret_cast<const float4*>(Wrow);
    {
        float av[4] = {fa.x, fa.y, fa.z, fa.w};
#pragma unroll
        for (int i = 0; i < 4; i++) As[0][lkk4 + i][lrA] = av[i];
        *reinterpret_cast<float4*>(&Ws[0][lkkw][lnn4]) = fw;
    }

    int buf = 0;
    for (int t = 0; t < KT; ++t) {
        __syncthreads();
        if (t + 1 < KT) {
            int k0 = (t + 1) * BK;
            fa = *reinterpret_cast<const float4*>(Arow + k0);
            fw = *reinterpret_cast<const float4*>(Wrow + (size_t)k0 * N);
        }
#pragma unroll
        for (int kk = 0; kk < BK; ++kk) {
            const unsigned long long* ap =
                reinterpret_cast<const unsigned long long*>(&As[buf][kk][ty * 4]);
            unsigned long long a01 = ap[0];
            unsigned long long a23 = ap[1];
            float4 w4 = *reinterpret_cast<const float4*>(&Ws[buf][kk][tx * 4]);
            unsigned long long wd[4];
            wd[0] = dup2(w4.x); wd[1] = dup2(w4.y); wd[2] = dup2(w4.z); wd[3] = dup2(w4.w);
#pragma unroll
            for (int j = 0; j < 4; j++) {
                ffma2(acc[0][j], a01, wd[j]);
                ffma2(acc[1][j], a23, wd[j]);
            }
        }
        if (t + 1 < KT) {
            int nb = buf ^ 1;
            float av[4] = {fa.x, fa.y, fa.z, fa.w};
#pragma unroll
            for (int i = 0; i < 4; i++) As[nb][lkk4 + i][lrA] = av[i];
            *reinterpret_cast<float4*>(&Ws[nb][lkkw][lnn4]) = fw;
        }
        buf ^= 1;
    }

    float bvv[4];
#pragma unroll
    for (int jj = 0; jj < 4; jj++)
        bvv[jj] = bias ? bias[col0 + tx * 4 + jj] : 0.f;
#pragma unroll
    for (int p = 0; p < 2; p++) {
        float2 f[4];
#pragma unroll
        for (int j = 0; j < 4; j++) f[j] = unpack2(acc[p][j]);
        int rbase = row0 + ty * 4 + 2 * p;
        int c = col0 + tx * 4;
#pragma unroll
        for (int lane = 0; lane < 2; lane++) {
            float4 o;
            o.x = (lane ? f[0].y : f[0].x) + bvv[0];
            o.y = (lane ? f[1].y : f[1].x) + bvv[1];
            o.z = (lane ? f[2].y : f[2].x) + bvv[2];
            o.w = (lane ? f[3].y : f[3].x) + bvv[3];
            *reinterpret_cast<float4*>(&C[(size_t)(rbase + lane) * N + c]) = o;
        }
    }
}

// ---------------- sos projection ----------------
__global__ __launch_bounds__(256) void sosproj_kernel(
    const float* __restrict__ sos, const float* __restrict__ w_ih,
    const float* __restrict__ b_ih, const float* __restrict__ b_hh) {
    __shared__ float part[4][64];
    int c = blockIdx.x * 64 + (threadIdx.x & 63);
    int seg = threadIdx.x >> 6;
    float acc = 0.f;
    for (int k = seg * 128; k < seg * 128 + 128; ++k)
        acc = fmaf(__ldg(&sos[k]), w_ih[(size_t)k * G4H + c], acc);
    part[seg][threadIdx.x & 63] = acc;
    __syncthreads();
    if (threadIdx.x < 64) {
        int cc = blockIdx.x * 64 + threadIdx.x;
        float s = part[0][threadIdx.x] + part[1][threadIdx.x] +
                  part[2][threadIdx.x] + part[3][threadIdx.x];
        g_sosproj[cc] = s + b_ih[cc] + b_hh[cc];
    }
}

// ---------------- init: c = 0 ----------------
__global__ void init_kernel() {
    int idx = blockIdx.x * blockDim.x + threadIdx.x;
    if (idx < B * H) g_c[idx] = 0.f;
}

// ---------------- standalone LSTM (t = 0 only) ----------------
__global__ __launch_bounds__(256) void lstm0_kernel() {
    int idx = blockIdx.x * blockDim.x + threadIdx.x;
    if (idx >= B * H / 4) return;
    int b = idx >> 7;
    int j = (idx & 127) * 4;
    const float* pr = g_Pg + (size_t)b * G4H;
    const float* ep = g_sosproj;
    float4 pi = *reinterpret_cast<const float4*>(pr + j);
    float4 pf = *reinterpret_cast<const float4*>(pr + H + j);
    float4 pg = *reinterpret_cast<const float4*>(pr + 2 * H + j);
    float4 po = *reinterpret_cast<const float4*>(pr + 3 * H + j);
    float4 ei = *reinterpret_cast<const float4*>(ep + j);
    float4 ef = *reinterpret_cast<const float4*>(ep + H + j);
    float4 eg = *reinterpret_cast<const float4*>(ep + 2 * H + j);
    float4 eo = *reinterpret_cast<const float4*>(ep + 3 * H + j);
    float4 cv = *reinterpret_cast<const float4*>(g_c + (size_t)b * H + j);
    float4 hn, cn;
    {
        float ig = sigmoidf_(pi.x + ei.x), fg = sigmoidf_(pf.x + ef.x);
        float gg = tanhf(pg.x + eg.x),     og = sigmoidf_(po.x + eo.x);
        cn.x = fg * cv.x + ig * gg; hn.x = og * tanhf(cn.x);
    }
    {
        float ig = sigmoidf_(pi.y + ei.y), fg = sigmoidf_(pf.y + ef.y);
        float gg = tanhf(pg.y + eg.y),     og = sigmoidf_(po.y + eo.y);
        cn.y = fg * cv.y + ig * gg; hn.y = og * tanhf(cn.y);
    }
    {
        float ig = sigmoidf_(pi.z + ei.z), fg = sigmoidf_(pf.z + ef.z);
        float gg = tanhf(pg.z + eg.z),     og = sigmoidf_(po.z + eo.z);
        cn.z = fg * cv.z + ig * gg; hn.z = og * tanhf(cn.z);
    }
    {
        float ig = sigmoidf_(pi.w + ei.w), fg = sigmoidf_(pf.w + ef.w);
        float gg = tanhf(pg.w + eg.w),     og = sigmoidf_(po.w + eo.w);
        cn.w = fg * cv.w + ig * gg; hn.w = og * tanhf(cn.w);
    }
    *reinterpret_cast<float4*>(g_c + (size_t)b * H + j) = cn;
    *reinterpret_cast<float4*>(g_h + (size_t)b * H + j) = hn;
}

// ------- sampleA (critical path): max/lse/argmax + seq/logp + fused LSTM -------
__global__ __launch_bounds__(256) void sampleA_kernel(
    float* __restrict__ o_seq, float* __restrict__ o_logp,
    uint32_t sk0, uint32_t sk1, int t)
{
    __shared__ float sred[256];
    __shared__ int   sredi[256];
    __shared__ float s_rowmax, s_lse;
    __shared__ int   s_sym;

    int b = blockIdx.x;
    int tid = threadIdx.x;
    const float* lr = g_logits + (size_t)(t & 1) * B * V + (size_t)b * V;

    float lv[8];
#pragma unroll
    for (int i = 0; i < 8; i++) lv[i] = lr[tid + 256 * i];

    float m = -3.402823466e38f;
#pragma unroll
    for (int i = 0; i < 8; i++) m = fmaxf(m, lv[i]);
    sred[tid] = m; __syncthreads();
    for (int s = 128; s > 0; s >>= 1) {
        if (tid < s) sred[tid] = fmaxf(sred[tid], sred[tid + s]);
        __syncthreads();
    }
    if (tid == 0) s_rowmax = sred[0];
    __syncthreads();
    float rowmax = s_rowmax;

    float sum = 0.f;
#pragma unroll
    for (int i = 0; i < 8; i++) sum += expf(lv[i] - rowmax);
    sred[tid] = sum; __syncthreads();
    for (int s = 128; s > 0; s >>= 1) {
        if (tid < s) sred[tid] += sred[tid + s];
        __syncthreads();
    }
    if (tid == 0) s_lse = logf(sred[0]);
    __syncthreads();
    float lse = s_lse;

    float best = -3.402823466e38f;
    int bestv = V;
    const float TINY = 1.17549435e-38f;
#pragma unroll
    for (int i = 0; i < 8; i++) {
        int v = tid + 256 * i;
        float lsm = lv[i] - rowmax - lse;
        uint32_t o0, o1;
        threefry2x32(sk0, sk1, 0u, (uint32_t)(b * V + v), o0, o1);
        uint32_t bits = o0 ^ o1;
        float uf = __uint_as_float(0x3f800000u | (bits >> 9)) - 1.0f;
        float u = fmaxf(TINY, uf + TINY);
        float g = -logf(-logf(u));
        float sc = lsm + g;
        if (sc > best) { best = sc; bestv = v; }
    }

    sred[tid] = best; sredi[tid] = bestv; __syncthreads();
    for (int s = 128; s > 0; s >>= 1) {
        if (tid < s) {
            float ov = sred[tid + s]; int oi = sredi[tid + s];
            if (ov > sred[tid] || (ov == sred[tid] && oi < sredi[tid])) {
                sred[tid] = ov; sredi[tid] = oi;
            }
        }
        __syncthreads();
    }
    if (tid == 0) {
        int sym = sredi[0];
        s_sym = sym;
        o_seq[b * L + t] = (float)sym;
        o_logp[b * L + t] = lr[sym] - rowmax - lse;
        g_mls[(t & 1) * B + b] = make_float2(rowmax, lse);
    }
    if (t >= MAX_LEN - 1) return;

    __syncthreads();
    int sym = s_sym;

    // fused LSTM for next step: 2 j-positions per thread
    int j = tid * 2;
    const float* pr = g_Pg + (size_t)b * G4H;
    const float* ep = g_eproj + (size_t)sym * G4H;
    float2 pi = *reinterpret_cast<const float2*>(pr + j);
    float2 pf = *reinterpret_cast<const float2*>(pr + H + j);
    float2 pg = *reinterpret_cast<const float2*>(pr + 2 * H + j);
    float2 po = *reinterpret_cast<const float2*>(pr + 3 * H + j);
    float2 ei = *reinterpret_cast<const float2*>(ep + j);
    float2 ef = *reinterpret_cast<const float2*>(ep + H + j);
    float2 eg = *reinterpret_cast<const float2*>(ep + 2 * H + j);
    float2 eo = *reinterpret_cast<const float2*>(ep + 3 * H + j);
    float2 cv = *reinterpret_cast<const float2*>(g_c + (size_t)b * H + j);
    float2 hn, cn;
    {
        float ig = sigmoidf_(pi.x + ei.x), fg = sigmoidf_(pf.x + ef.x);
        float gg = tanhf(pg.x + eg.x),     og = sigmoidf_(po.x + eo.x);
        cn.x = fg * cv.x + ig * gg; hn.x = og * tanhf(cn.x);
    }
    {
        float ig = sigmoidf_(pi.y + ei.y), fg = sigmoidf_(pf.y + ef.y);
        float gg = tanhf(pg.y + eg.y),     og = sigmoidf_(po.y + eo.y);
        cn.y = fg * cv.y + ig * gg; hn.y = og * tanhf(cn.y);
    }
    *reinterpret_cast<float2*>(g_c + (size_t)b * H + j) = cn;
    *reinterpret_cast<float2*>(g_h + (size_t)b * H + j) = hn;
}

// ------- sampleB (side stream): probs + entropy, identical order -------
__global__ __launch_bounds__(256) void sampleB_kernel(
    float* __restrict__ o_probs, float* __restrict__ o_ent, int t)
{
    __shared__ float sred[256];
    int b = blockIdx.x;
    int tid = threadIdx.x;
    const float* lr = g_logits + (size_t)(t & 1) * B * V + (size_t)b * V;
    float2 ml = g_mls[(t & 1) * B + b];
    float rowmax = ml.x, lse = ml.y;

    float entacc = 0.f;
    size_t pbase = ((size_t)b * L + t) * V;
    for (int v = tid; v < V; v += 256) {
        float lsm = lr[v] - rowmax - lse;
        float p = expf(lsm);
        o_probs[pbase + v] = p;
        entacc += p * lsm;
    }
    sred[tid] = entacc; __syncthreads();
    for (int s = 128; s > 0; s >>= 1) {
        if (tid < s) sred[tid] += sred[tid + s];
        __syncthreads();
    }
    if (tid == 0) o_ent[b * L + t] = -sred[0];
}

// ---------------- EOS step (t = 32) ----------------
__global__ void eos_kernel(float* __restrict__ o_seq, float* __restrict__ o_probs,
                           float* __restrict__ o_logp, float* __restrict__ o_ent) {
    int idx = blockIdx.x * blockDim.x + threadIdx.x;
    if (idx < B * V) {
        int b = idx / V, v = idx % V;
        o_probs[((size_t)b * L + MAX_LEN) * V + v] = 1.0f;
    }
    if (idx < B) {
        o_seq[idx * L + MAX_LEN]  = 0.f;
        o_logp[idx * L + MAX_LEN] = 0.f;
        o_ent[idx * L + MAX_LEN]  = 0.f;
    }
}

// ---------------- launch ----------------
extern "C" void kernel_launch(void* const* d_in, const int* in_sizes, int n_in,
                              void* d_out, int out_size) {
    const float* x         = (const float*)d_in[0];
    const float* agent_w   = (const float*)d_in[1];
    const float* agent_b   = (const float*)d_in[2];
    const float* sos       = (const float*)d_in[3];
    const float* embedding = (const float*)d_in[4];
    const float* w_ih      = (const float*)d_in[5];
    const float* w_hh      = (const float*)d_in[6];
    const float* b_ih      = (const float*)d_in[7];
    const float* b_hh      = (const float*)d_in[8];
    const float* out_w     = (const float*)d_in[9];
    const float* out_b     = (const float*)d_in[10];

    float* out = (float*)d_out;
    float* o_seq   = out;
    float* o_probs = out + (size_t)B * L;
    float* o_logp  = o_probs + (size_t)B * L * V;
    float* o_ent   = o_logp + (size_t)B * L;

    static float *dh = nullptr, *dPg = nullptr, *dl = nullptr, *dep = nullptr;
    static cudaStream_t s2;
    static cudaEvent_t e0, e1, evA, evB[2];
    if (!dh) {
        cudaGetSymbolAddress((void**)&dh, g_h);
        cudaGetSymbolAddress((void**)&dPg, g_Pg);
        cudaGetSymbolAddress((void**)&dl, g_logits);
        cudaGetSymbolAddress((void**)&dep, g_eproj);
        cudaStreamCreateWithFlags(&s2, cudaStreamNonBlocking);
        cudaEventCreateWithFlags(&e0, cudaEventDisableTiming);
        cudaEventCreateWithFlags(&e1, cudaEventDisableTiming);
        cudaEventCreateWithFlags(&evA, cudaEventDisableTiming);
        cudaEventCreateWithFlags(&evB[0], cudaEventDisableTiming);
        cudaEventCreateWithFlags(&evB[1], cudaEventDisableTiming);
    }

    init_kernel<<<(B * H + 255) / 256, 256>>>();
    cudaEventRecord(e0, 0);

    // side stream: emb_proj = embedding @ w_ih + b_ih + b_hh
    cudaStreamWaitEvent(s2, e0, 0);
    gemm2_kernel<<<dim3(G4H / BN, V / BM), 256, 0, s2>>>(
        embedding, E_DIM, w_ih, b_ih, b_hh, dep, G4H,
        nullptr, nullptr, nullptr, 0, 0);
    cudaEventRecord(e1, s2);

    // main stream prologue
    sosproj_kernel<<<32, 256>>>(sos, w_ih, b_ih, b_hh);
    gemm64_kernel<<<dim3(H / 64, B / 64), 256>>>(x, IN_DIM, agent_w, agent_b, dh, H);
    gemm2_kernel<<<dim3(G4H / BN, B / BM), 256>>>(
        dh, H, w_hh, nullptr, nullptr, dPg, G4H,
        nullptr, nullptr, nullptr, 0, 0);
    lstm0_kernel<<<(B * H / 4 + 255) / 256, 256>>>();

    // JAX key chain: key0 = key(1) = (0,1)
    uint32_t k0 = 0u, k1 = 1u;
    for (int t = 0; t < MAX_LEN; ++t) {
        uint32_t n0, n1, s0cap, s1cap;
        threefry2x32(k0, k1, 0u, 0u, n0, n1);
        threefry2x32(k0, k1, 0u, 1u, s0cap, s1cap);

        float* dlt = dl + (size_t)(t & 1) * B * V;   // logits buffer, parity t

        // gemm(t) writes logits[t&1]; sampleB(t-2) must be done reading it
        if (t >= 2) cudaStreamWaitEvent(0, evB[t & 1], 0);

        // combined: Pg(next) = h@w_hh ; logits = h@out_w + out_b (128x128 tiles)
        if (t < MAX_LEN - 1) {
            gemm2_kernel<<<dim3((G4H + V) / BN, B / BM), 256>>>(
                dh, H, w_hh, nullptr, nullptr, dPg, G4H,
                out_w, out_b, dlt, V, 0);
        } else {
            gemm2_kernel<<<dim3(V / BN, B / BM), 256>>>(
                dh, H, w_hh, nullptr, nullptr, dPg, G4H,
                out_w, out_b, dlt, V, G4H);
        }

        if (t == 0) cudaStreamWaitEvent(0, e1, 0);  // eproj ready before fused lstm

        // critical: sample + fused next-step lstm
        sampleA_kernel<<<B, 256>>>(o_seq, o_logp, s0cap, s1cap, t);
        cudaEventRecord(evA, 0);

        // side: probs + entropy (overlaps next step's gemm)
        cudaStreamWaitEvent(s2, evA, 0);
        sampleB_kernel<<<B, 256, 0, s2>>>(o_probs, o_ent, t);
        cudaEventRecord(evB[t & 1], s2);

        k0 = n0; k1 = n1;
    }

    // join side stream before epilogue
    cudaStreamWaitEvent(0, evB[0], 0);
    cudaStreamWaitEvent(0, evB[1], 0);
    eos_kernel<<<(B * V + 255) / 256, 256>>>(o_seq, o_probs, o_logp, o_ent);
}

// round 14
// speedup vs baseline: 3.4025x; 2.6631x over previous
#include <cuda_runtime.h>
#include <cstdint>
#include <math.h>

#define B 512
#define IN_DIM 1024
#define H 512
#define E_DIM 512
#define V 2048
#define MAX_LEN 32
#define L 33
#define G4H (4 * H)

// ---------------- scratch (no allocations allowed) ----------------
__device__ float g_h[B * H];
__device__ float g_c[B * H];
__device__ float g_Pg[(size_t)B * G4H];        // h @ w_hh partial gates
__device__ float g_logits[(size_t)B * V];
__device__ float g_eproj[(size_t)V * G4H];     // embedding @ w_ih + b_ih + b_hh
__device__ float g_sosproj[G4H];               // sos @ w_ih + b_ih + b_hh

// ---------------- threefry2x32 (JAX-compatible, 20 rounds) ----------------
__host__ __device__ __forceinline__ uint32_t rotl32(uint32_t v, int d) {
    return (v << d) | (v >> (32 - d));
}

__host__ __device__ __forceinline__ void threefry2x32(uint32_t k0, uint32_t k1,
                                                      uint32_t x0, uint32_t x1,
                                                      uint32_t& o0, uint32_t& o1) {
    uint32_t ks2 = k0 ^ k1 ^ 0x1BD11BDAu;
    x0 += k0; x1 += k1;
#define TF_R(r) { x0 += x1; x1 = rotl32(x1, r); x1 ^= x0; }
    TF_R(13) TF_R(15) TF_R(26) TF_R(6)
    x0 += k1; x1 += ks2 + 1u;
    TF_R(17) TF_R(29) TF_R(16) TF_R(24)
    x0 += ks2; x1 += k0 + 2u;
    TF_R(13) TF_R(15) TF_R(26) TF_R(6)
    x0 += k0; x1 += k1 + 3u;
    TF_R(17) TF_R(29) TF_R(16) TF_R(24)
    x0 += k1; x1 += ks2 + 4u;
    TF_R(13) TF_R(15) TF_R(26) TF_R(6)
    x0 += ks2; x1 += k0 + 5u;
#undef TF_R
    o0 = x0; o1 = x1;
}

__device__ __forceinline__ float sigmoidf_(float x) {
    // XLA logistic expansion: 0.5 + 0.5 * tanh(0.5 * x)
    return 0.5f + 0.5f * tanhf(0.5f * x);
}

// ---------------- packed f32x2 helpers ----------------
__device__ __forceinline__ void ffma2(unsigned long long& acc, unsigned long long a,
                                      unsigned long long b) {
    asm("fma.rn.f32x2 %0, %1, %2, %0;" : "+l"(acc) : "l"(a), "l"(b));
}
__device__ __forceinline__ unsigned long long dup2(float w) {
    unsigned long long r;
    asm("mov.b64 %0, {%1, %1};" : "=l"(r) : "r"(__float_as_uint(w)));
    return r;
}
__device__ __forceinline__ float2 unpack2(unsigned long long v) {
    float2 f;
    asm("mov.b64 {%0, %1}, %2;" : "=f"(f.x), "=f"(f.y) : "l"(v));
    return f;
}

// ---------------- FFMA2 GEMM: C = A @ W (+bias), split-column dual output ----------
// EXACT r2/r7 configuration (best measured): BM=128, BN=128, BK=16, 256 threads,
// 8x8/thread, W tile NOT duplicated (dup2 MOVs run on the ALU pipe in parallel).
#define BM 128
#define BN 128
#define BK 16
#define ASTRIDE 130
#define WSTRIDE 132

__global__ __launch_bounds__(256, 2) void gemm2_kernel(
    const float* __restrict__ A, int K,
    const float* __restrict__ W1, const float* __restrict__ b1a, const float* __restrict__ b1b,
    float* __restrict__ C1, int N1,
    const float* __restrict__ W2, const float* __restrict__ b2a,
    float* __restrict__ C2, int N2, int col_base)
{
    __shared__ float As[2][BK][ASTRIDE];
    __shared__ float Ws[2][BK][WSTRIDE];

    const int tid = threadIdx.x;
    const int tx = tid & 15;           // 0..15 (N)
    const int ty = tid >> 4;           // 0..15 (M)
    const int row0 = blockIdx.y * BM;
    const int col0 = blockIdx.x * BN + col_base;

    const float* W; const float* ba; const float* bb; float* C; int ldN; int cloc0;
    if (col0 < N1) { W = W1; ba = b1a; bb = b1b; C = C1; ldN = N1; cloc0 = col0; }
    else           { W = W2; ba = b2a; bb = nullptr; C = C2; ldN = N2; cloc0 = col0 - N1; }

    // loader indices
    const int lrA  = tid >> 2;               // 0..63
    const int lkk4 = (tid & 3) * 4;          // 0,4,8,12
    const int lkkw = tid >> 4;               // 0..15
    const int lnn4 = (tid & 15) * 4;         // 0..60

    const float* Arow0 = A + (size_t)(row0 + lrA) * K + lkk4;
    const float* Arow1 = A + (size_t)(row0 + lrA + 64) * K + lkk4;
    const float* Wrow  = W + (size_t)lkkw * ldN + cloc0;

    unsigned long long acc[4][8];
#pragma unroll
    for (int p = 0; p < 4; p++)
#pragma unroll
        for (int j = 0; j < 8; j++) acc[p][j] = 0ull;

    const int KT = K / BK;
    float4 fa0, fa1, fw0, fw1;

    // prefetch tile 0
    fa0 = *reinterpret_cast<const float4*>(Arow0);
    fa1 = *reinterpret_cast<const float4*>(Arow1);
    fw0 = *reinterpret_cast<const float4*>(Wrow + lnn4);
    fw1 = *reinterpret_cast<const float4*>(Wrow + 64 + lnn4);
    {
        float av0[4] = {fa0.x, fa0.y, fa0.z, fa0.w};
        float av1[4] = {fa1.x, fa1.y, fa1.z, fa1.w};
#pragma unroll
        for (int i = 0; i < 4; i++) {
            As[0][lkk4 + i][lrA] = av0[i];
            As[0][lkk4 + i][lrA + 64] = av1[i];
        }
        *reinterpret_cast<float4*>(&Ws[0][lkkw][lnn4]) = fw0;
        *reinterpret_cast<float4*>(&Ws[0][lkkw][64 + lnn4]) = fw1;
    }

    int buf = 0;
    for (int t = 0; t < KT; ++t) {
        __syncthreads();
        if (t + 1 < KT) {
            int k0 = (t + 1) * BK;
            fa0 = *reinterpret_cast<const float4*>(Arow0 + k0);
            fa1 = *reinterpret_cast<const float4*>(Arow1 + k0);
            fw0 = *reinterpret_cast<const float4*>(Wrow + (size_t)k0 * ldN + lnn4);
            fw1 = *reinterpret_cast<const float4*>(Wrow + (size_t)k0 * ldN + 64 + lnn4);
        }

#pragma unroll
        for (int kk = 0; kk < BK; ++kk) {
            const unsigned long long* ap0 =
                reinterpret_cast<const unsigned long long*>(&As[buf][kk][ty * 4]);
            const unsigned long long* ap1 =
                reinterpret_cast<const unsigned long long*>(&As[buf][kk][64 + ty * 4]);
            unsigned long long a01 = ap0[0];
            unsigned long long a23 = ap0[1];
            unsigned long long a45 = ap1[0];
            unsigned long long a67 = ap1[1];
            float4 w03 = *reinterpret_cast<const float4*>(&Ws[buf][kk][tx * 4]);
            float4 w47 = *reinterpret_cast<const float4*>(&Ws[buf][kk][64 + tx * 4]);
            unsigned long long wd[8];
            wd[0] = dup2(w03.x); wd[1] = dup2(w03.y); wd[2] = dup2(w03.z); wd[3] = dup2(w03.w);
            wd[4] = dup2(w47.x); wd[5] = dup2(w47.y); wd[6] = dup2(w47.z); wd[7] = dup2(w47.w);
#pragma unroll
            for (int j = 0; j < 8; j++) {
                ffma2(acc[0][j], a01, wd[j]);
                ffma2(acc[1][j], a23, wd[j]);
                ffma2(acc[2][j], a45, wd[j]);
                ffma2(acc[3][j], a67, wd[j]);
            }
        }

        if (t + 1 < KT) {
            int nb = buf ^ 1;
            float av0[4] = {fa0.x, fa0.y, fa0.z, fa0.w};
            float av1[4] = {fa1.x, fa1.y, fa1.z, fa1.w};
#pragma unroll
            for (int i = 0; i < 4; i++) {
                As[nb][lkk4 + i][lrA] = av0[i];
                As[nb][lkk4 + i][lrA + 64] = av1[i];
            }
            *reinterpret_cast<float4*>(&Ws[nb][lkkw][lnn4]) = fw0;
            *reinterpret_cast<float4*>(&Ws[nb][lkkw][64 + lnn4]) = fw1;
        }
        buf ^= 1;
    }

    // epilogue: bias + store (float4 per row / col-group)
    float bv[2][4];
#pragma unroll
    for (int g = 0; g < 2; g++) {
        int cb = cloc0 + g * 64 + tx * 4;
#pragma unroll
        for (int jj = 0; jj < 4; jj++) {
            float v = 0.f;
            if (ba) v += ba[cb + jj];
            if (bb) v += bb[cb + jj];
            bv[g][jj] = v;
        }
    }
#pragma unroll
    for (int hh = 0; hh < 2; hh++) {
#pragma unroll
        for (int pp = 0; pp < 2; pp++) {
            int p = hh * 2 + pp;
            float2 f[8];
#pragma unroll
            for (int j = 0; j < 8; j++) f[j] = unpack2(acc[p][j]);
            int rbase = row0 + hh * 64 + ty * 4 + 2 * pp;
#pragma unroll
            for (int lane = 0; lane < 2; lane++) {
                int r = rbase + lane;
#pragma unroll
                for (int g = 0; g < 2; g++) {
                    int c = cloc0 + g * 64 + tx * 4;
                    float4 o;
                    o.x = (lane ? f[g * 4 + 0].y : f[g * 4 + 0].x) + bv[g][0];
                    o.y = (lane ? f[g * 4 + 1].y : f[g * 4 + 1].x) + bv[g][1];
                    o.z = (lane ? f[g * 4 + 2].y : f[g * 4 + 2].x) + bv[g][2];
                    o.w = (lane ? f[g * 4 + 3].y : f[g * 4 + 3].x) + bv[g][3];
                    *reinterpret_cast<float4*>(&C[(size_t)r * ldN + c]) = o;
                }
            }
        }
    }
}

// ---------------- 64x64-tile GEMM (h0 prologue) ----------------
#define ASTR64 66
#define WSTR64 68

__global__ __launch_bounds__(256, 2) void gemm64_kernel(
    const float* __restrict__ A, int K,
    const float* __restrict__ W, const float* __restrict__ bias,
    float* __restrict__ C, int N)
{
    __shared__ float As[2][BK][ASTR64];
    __shared__ float Ws[2][BK][WSTR64];

    const int tid = threadIdx.x;
    const int tx = tid & 15;
    const int ty = tid >> 4;
    const int row0 = blockIdx.y * 64;
    const int col0 = blockIdx.x * 64;

    const int lrA  = tid >> 2;
    const int lkk4 = (tid & 3) * 4;
    const int lkkw = tid >> 4;
    const int lnn4 = (tid & 15) * 4;

    const float* Arow = A + (size_t)(row0 + lrA) * K + lkk4;
    const float* Wrow = W + (size_t)lkkw * N + col0 + lnn4;

    unsigned long long acc[2][4];
#pragma unroll
    for (int p = 0; p < 2; p++)
#pragma unroll
        for (int j = 0; j < 4; j++) acc[p][j] = 0ull;

    const int KT = K / BK;
    float4 fa, fw;

    fa = *reinterpret_cast<const float4*>(Arow);
    fw = *reinterpret_cast<const float4*>(Wrow);
    {
        float av[4] = {fa.x, fa.y, fa.z, fa.w};
#pragma unroll
        for (int i = 0; i < 4; i++) As[0][lkk4 + i][lrA] = av[i];
        *reinterpret_cast<float4*>(&Ws[0][lkkw][lnn4]) = fw;
    }

    int buf = 0;
    for (int t = 0; t < KT; ++t) {
        __syncthreads();
        if (t + 1 < KT) {
            int k0 = (t + 1) * BK;
            fa = *reinterpret_cast<const float4*>(Arow + k0);
            fw = *reinterpret_cast<const float4*>(Wrow + (size_t)k0 * N);
        }

#pragma unroll
        for (int kk = 0; kk < BK; ++kk) {
            const unsigned long long* ap =
                reinterpret_cast<const unsigned long long*>(&As[buf][kk][ty * 4]);
            unsigned long long a01 = ap[0];
            unsigned long long a23 = ap[1];
            float4 w4 = *reinterpret_cast<const float4*>(&Ws[buf][kk][tx * 4]);
            unsigned long long wd[4];
            wd[0] = dup2(w4.x); wd[1] = dup2(w4.y); wd[2] = dup2(w4.z); wd[3] = dup2(w4.w);
#pragma unroll
            for (int j = 0; j < 4; j++) {
                ffma2(acc[0][j], a01, wd[j]);
                ffma2(acc[1][j], a23, wd[j]);
            }
        }

        if (t + 1 < KT) {
            int nb = buf ^ 1;
            float av[4] = {fa.x, fa.y, fa.z, fa.w};
#pragma unroll
            for (int i = 0; i < 4; i++) As[nb][lkk4 + i][lrA] = av[i];
            *reinterpret_cast<float4*>(&Ws[nb][lkkw][lnn4]) = fw;
        }
        buf ^= 1;
    }

    float bvv[4];
#pragma unroll
    for (int jj = 0; jj < 4; jj++)
        bvv[jj] = bias ? bias[col0 + tx * 4 + jj] : 0.f;
#pragma unroll
    for (int p = 0; p < 2; p++) {
        float2 f[4];
#pragma unroll
        for (int j = 0; j < 4; j++) f[j] = unpack2(acc[p][j]);
        int rbase = row0 + ty * 4 + 2 * p;
        int c = col0 + tx * 4;
#pragma unroll
        for (int lane = 0; lane < 2; lane++) {
            float4 o;
            o.x = (lane ? f[0].y : f[0].x) + bvv[0];
            o.y = (lane ? f[1].y : f[1].x) + bvv[1];
            o.z = (lane ? f[2].y : f[2].x) + bvv[2];
            o.w = (lane ? f[3].y : f[3].x) + bvv[3];
            *reinterpret_cast<float4*>(&C[(size_t)(rbase + lane) * N + c]) = o;
        }
    }
}

// ---------------- sos projection: sos @ w_ih + b_ih + b_hh ----------------
__global__ __launch_bounds__(256) void sosproj_kernel(
    const float* __restrict__ sos, const float* __restrict__ w_ih,
    const float* __restrict__ b_ih, const float* __restrict__ b_hh) {
    __shared__ float part[4][64];
    int c = blockIdx.x * 64 + (threadIdx.x & 63);
    int seg = threadIdx.x >> 6;               // 0..3
    float acc = 0.f;
    for (int k = seg * 128; k < seg * 128 + 128; ++k)
        acc = fmaf(__ldg(&sos[k]), w_ih[(size_t)k * G4H + c], acc);
    part[seg][threadIdx.x & 63] = acc;
    __syncthreads();
    if (threadIdx.x < 64) {
        int cc = blockIdx.x * 64 + threadIdx.x;
        float s = part[0][threadIdx.x] + part[1][threadIdx.x] +
                  part[2][threadIdx.x] + part[3][threadIdx.x];
        g_sosproj[cc] = s + b_ih[cc] + b_hh[cc];
    }
}

// ---------------- init: c = 0 ----------------
__global__ void init_kernel() {
    int idx = blockIdx.x * blockDim.x + threadIdx.x;
    if (idx < B * H) g_c[idx] = 0.f;
}

// ---------------- standalone LSTM (t = 0 only): Pg + sosproj -> h, c ----------------
__global__ __launch_bounds__(256) void lstm0_kernel() {
    int idx = blockIdx.x * blockDim.x + threadIdx.x;   // B*H/4 threads
    if (idx >= B * H / 4) return;
    int b = idx >> 7;
    int j = (idx & 127) * 4;
    const float* pr = g_Pg + (size_t)b * G4H;
    const float* ep = g_sosproj;
    float4 pi = *reinterpret_cast<const float4*>(pr + j);
    float4 pf = *reinterpret_cast<const float4*>(pr + H + j);
    float4 pg = *reinterpret_cast<const float4*>(pr + 2 * H + j);
    float4 po = *reinterpret_cast<const float4*>(pr + 3 * H + j);
    float4 ei = *reinterpret_cast<const float4*>(ep + j);
    float4 ef = *reinterpret_cast<const float4*>(ep + H + j);
    float4 eg = *reinterpret_cast<const float4*>(ep + 2 * H + j);
    float4 eo = *reinterpret_cast<const float4*>(ep + 3 * H + j);
    float4 cv = *reinterpret_cast<const float4*>(g_c + (size_t)b * H + j);
    float4 hn, cn;
    {
        float ig = sigmoidf_(pi.x + ei.x), fg = sigmoidf_(pf.x + ef.x);
        float gg = tanhf(pg.x + eg.x),     og = sigmoidf_(po.x + eo.x);
        cn.x = fg * cv.x + ig * gg; hn.x = og * tanhf(cn.x);
    }
    {
        float ig = sigmoidf_(pi.y + ei.y), fg = sigmoidf_(pf.y + ef.y);
        float gg = tanhf(pg.y + eg.y),     og = sigmoidf_(po.y + eo.y);
        cn.y = fg * cv.y + ig * gg; hn.y = og * tanhf(cn.y);
    }
    {
        float ig = sigmoidf_(pi.z + ei.z), fg = sigmoidf_(pf.z + ef.z);
        float gg = tanhf(pg.z + eg.z),     og = sigmoidf_(po.z + eo.z);
        cn.z = fg * cv.z + ig * gg; hn.z = og * tanhf(cn.z);
    }
    {
        float ig = sigmoidf_(pi.w + ei.w), fg = sigmoidf_(pf.w + ef.w);
        float gg = tanhf(pg.w + eg.w),     og = sigmoidf_(po.w + eo.w);
        cn.w = fg * cv.w + ig * gg; hn.w = og * tanhf(cn.w);
    }
    *reinterpret_cast<float4*>(g_c + (size_t)b * H + j) = cn;
    *reinterpret_cast<float4*>(g_h + (size_t)b * H + j) = hn;
}

// ------- monolithic sample: register-resident logits, outputs, fused LSTM -------
// Identical reduction/summation orders to the measured r7 kernel; logits are
// read ONCE into 8 regs/thread instead of 3 global passes.
__global__ __launch_bounds__(256) void sample_kernel(
    float* __restrict__ o_seq, float* __restrict__ o_probs,
    float* __restrict__ o_logp, float* __restrict__ o_ent,
    uint32_t sk0, uint32_t sk1, int t)
{
    __shared__ float sred[256];
    __shared__ int   sredi[256];
    __shared__ float s_rowmax, s_lse;
    __shared__ int   s_sym;

    int b = blockIdx.x;
    int tid = threadIdx.x;
    const float* lr = g_logits + (size_t)b * V;

    float lv[8];
#pragma unroll
    for (int i = 0; i < 8; i++) lv[i] = lr[tid + 256 * i];

    // row max (thread-sequential then tree — same order as r7)
    float m = -3.402823466e38f;
#pragma unroll
    for (int i = 0; i < 8; i++) m = fmaxf(m, lv[i]);
    sred[tid] = m; __syncthreads();
    for (int s = 128; s > 0; s >>= 1) {
        if (tid < s) sred[tid] = fmaxf(sred[tid], sred[tid + s]);
        __syncthreads();
    }
    if (tid == 0) s_rowmax = sred[0];
    __syncthreads();
    float rowmax = s_rowmax;

    // log-sum-exp
    float sum = 0.f;
#pragma unroll
    for (int i = 0; i < 8; i++) sum += expf(lv[i] - rowmax);
    sred[tid] = sum; __syncthreads();
    for (int s = 128; s > 0; s >>= 1) {
        if (tid < s) sred[tid] += sred[tid + s];
        __syncthreads();
    }
    if (tid == 0) s_lse = logf(sred[0]);
    __syncthreads();
    float lse = s_lse;

    // probs / entropy / gumbel argmax
    float entacc = 0.f;
    float best = -3.402823466e38f;
    int bestv = V;
    size_t pbase = ((size_t)b * L + t) * V;
    const float TINY = 1.17549435e-38f;
#pragma unroll
    for (int i = 0; i < 8; i++) {
        int v = tid + 256 * i;
        float lsm = lv[i] - rowmax - lse;
        float p = expf(lsm);
        o_probs[pbase + v] = p;
        entacc += p * lsm;
        uint32_t o0, o1;
        threefry2x32(sk0, sk1, 0u, (uint32_t)(b * V + v), o0, o1);
        uint32_t bits = o0 ^ o1;
        float uf = __uint_as_float(0x3f800000u | (bits >> 9)) - 1.0f;
        float u = fmaxf(TINY, uf + TINY);
        float g = -logf(-logf(u));
        float sc = lsm + g;
        if (sc > best) { best = sc; bestv = v; }
    }

    // entropy reduce
    __syncthreads();
    sred[tid] = entacc; __syncthreads();
    for (int s = 128; s > 0; s >>= 1) {
        if (tid < s) sred[tid] += sred[tid + s];
        __syncthreads();
    }
    float entropy = -sred[0];
    __syncthreads();

    // argmax reduce (first-index tie-break)
    sred[tid] = best; sredi[tid] = bestv; __syncthreads();
    for (int s = 128; s > 0; s >>= 1) {
        if (tid < s) {
            float ov = sred[tid + s]; int oi = sredi[tid + s];
            if (ov > sred[tid] || (ov == sred[tid] && oi < sredi[tid])) {
                sred[tid] = ov; sredi[tid] = oi;
            }
        }
        __syncthreads();
    }
    if (tid == 0) {
        int sym = sredi[0];
        s_sym = sym;
        o_seq[b * L + t] = (float)sym;
        o_ent[b * L + t] = entropy;
        o_logp[b * L + t] = lr[sym] - rowmax - lse;
    }
    if (t >= MAX_LEN - 1) return;

    __syncthreads();
    int sym = s_sym;

    // fused LSTM for next step: 2 j-positions per thread (float2)
    int j = tid * 2;
    const float* pr = g_Pg + (size_t)b * G4H;
    const float* ep = g_eproj + (size_t)sym * G4H;
    float2 pi = *reinterpret_cast<const float2*>(pr + j);
    float2 pf = *reinterpret_cast<const float2*>(pr + H + j);
    float2 pg = *reinterpret_cast<const float2*>(pr + 2 * H + j);
    float2 po = *reinterpret_cast<const float2*>(pr + 3 * H + j);
    float2 ei = *reinterpret_cast<const float2*>(ep + j);
    float2 ef = *reinterpret_cast<const float2*>(ep + H + j);
    float2 eg = *reinterpret_cast<const float2*>(ep + 2 * H + j);
    float2 eo = *reinterpret_cast<const float2*>(ep + 3 * H + j);
    float2 cv = *reinterpret_cast<const float2*>(g_c + (size_t)b * H + j);
    float2 hn, cn;
    {
        float ig = sigmoidf_(pi.x + ei.x), fg = sigmoidf_(pf.x + ef.x);
        float gg = tanhf(pg.x + eg.x),     og = sigmoidf_(po.x + eo.x);
        cn.x = fg * cv.x + ig * gg; hn.x = og * tanhf(cn.x);
    }
    {
        float ig = sigmoidf_(pi.y + ei.y), fg = sigmoidf_(pf.y + ef.y);
        float gg = tanhf(pg.y + eg.y),     og = sigmoidf_(po.y + eo.y);
        cn.y = fg * cv.y + ig * gg; hn.y = og * tanhf(cn.y);
    }
    *reinterpret_cast<float2*>(g_c + (size_t)b * H + j) = cn;
    *reinterpret_cast<float2*>(g_h + (size_t)b * H + j) = hn;
}

// ---------------- EOS step (t = 32): zeros + probs of ones ----------------
__global__ void eos_kernel(float* __restrict__ o_seq, float* __restrict__ o_probs,
                           float* __restrict__ o_logp, float* __restrict__ o_ent) {
    int idx = blockIdx.x * blockDim.x + threadIdx.x;
    if (idx < B * V) {
        int b = idx / V, v = idx % V;
        o_probs[((size_t)b * L + MAX_LEN) * V + v] = 1.0f;
    }
    if (idx < B) {
        o_seq[idx * L + MAX_LEN]  = 0.f;
        o_logp[idx * L + MAX_LEN] = 0.f;
        o_ent[idx * L + MAX_LEN]  = 0.f;
    }
}

// ---------------- launch ----------------
extern "C" void kernel_launch(void* const* d_in, const int* in_sizes, int n_in,
                              void* d_out, int out_size) {
    const float* x         = (const float*)d_in[0];
    const float* agent_w   = (const float*)d_in[1];
    const float* agent_b   = (const float*)d_in[2];
    const float* sos       = (const float*)d_in[3];
    const float* embedding = (const float*)d_in[4];
    const float* w_ih      = (const float*)d_in[5];
    const float* w_hh      = (const float*)d_in[6];
    const float* b_ih      = (const float*)d_in[7];
    const float* b_hh      = (const float*)d_in[8];
    const float* out_w     = (const float*)d_in[9];
    const float* out_b     = (const float*)d_in[10];

    float* out = (float*)d_out;
    float* o_seq   = out;                                   // [B, 33]
    float* o_probs = out + (size_t)B * L;                   // [B, 33, V]
    float* o_logp  = o_probs + (size_t)B * L * V;           // [B, 33]
    float* o_ent   = o_logp + (size_t)B * L;                // [B, 33]

    static float *dh = nullptr, *dPg = nullptr, *dl = nullptr, *dep = nullptr;
    static cudaStream_t s2;
    static cudaEvent_t e0, e1;
    if (!dh) {
        cudaGetSymbolAddress((void**)&dh, g_h);
        cudaGetSymbolAddress((void**)&dPg, g_Pg);
        cudaGetSymbolAddress((void**)&dl, g_logits);
        cudaGetSymbolAddress((void**)&dep, g_eproj);
        cudaStreamCreateWithFlags(&s2, cudaStreamNonBlocking);
        cudaEventCreateWithFlags(&e0, cudaEventDisableTiming);
        cudaEventCreateWithFlags(&e1, cudaEventDisableTiming);
    }

    init_kernel<<<(B * H + 255) / 256, 256>>>();
    cudaEventRecord(e0, 0);

    // side stream: emb_proj = embedding @ w_ih + b_ih + b_hh
    // (first consumed by the fused lstm tail of sample(t=0))
    cudaStreamWaitEvent(s2, e0, 0);
    gemm2_kernel<<<dim3(G4H / BN, V / BM), 256, 0, s2>>>(
        embedding, E_DIM, w_ih, b_ih, b_hh, dep, G4H,
        nullptr, nullptr, nullptr, 0, 0);
    cudaEventRecord(e1, s2);

    // main stream prologue
    sosproj_kernel<<<32, 256>>>(sos, w_ih, b_ih, b_hh);

    // h0 = x @ agent_w + agent_b   (M=512, N=512, K=1024) — 64x64 tiles, grid=64
    gemm64_kernel<<<dim3(H / 64, B / 64), 256>>>(x, IN_DIM, agent_w, agent_b, dh, H);

    // Pg0 = h0 @ w_hh   (M=512, N=2048, K=512)
    gemm2_kernel<<<dim3(G4H / BN, B / BM), 256>>>(
        dh, H, w_hh, nullptr, nullptr, dPg, G4H,
        nullptr, nullptr, nullptr, 0, 0);

    // lstm for step 0 (sosproj path)
    lstm0_kernel<<<(B * H / 4 + 255) / 256, 256>>>();

    // JAX key chain: key0 = key(1) = (0,1)
    uint32_t k0 = 0u, k1 = 1u;
    for (int t = 0; t < MAX_LEN; ++t) {
        uint32_t n0, n1, s0cap, s1cap;
        threefry2x32(k0, k1, 0u, 0u, n0, n1);
        threefry2x32(k0, k1, 0u, 1u, s0cap, s1cap);

        // combined: Pg(next) = h@w_hh ; logits = h@out_w + out_b
        if (t < MAX_LEN - 1) {
            gemm2_kernel<<<dim3((G4H + V) / BN, B / BM), 256>>>(
                dh, H, w_hh, nullptr, nullptr, dPg, G4H,
                out_w, out_b, dl, V, 0);
        } else {
            gemm2_kernel<<<dim3(V / BN, B / BM), 256>>>(
                dh, H, w_hh, nullptr, nullptr, dPg, G4H,
                out_w, out_b, dl, V, G4H);
        }

        if (t == 0) cudaStreamWaitEvent(0, e1, 0);  // eproj ready before fused lstm

        // sample + outputs + fused next-step lstm
        sample_kernel<<<B, 256>>>(o_seq, o_probs, o_logp, o_ent, s0cap, s1cap, t);

        k0 = n0; k1 = n1;
    }

    eos_kernel<<<(B * V + 255) / 256, 256>>>(o_seq, o_probs, o_logp, o_ent);
}